// round 1
// baseline (speedup 1.0000x reference)
#include <cuda_runtime.h>
#include <math.h>

// Problem constants
#define B_   8
#define NQ_  1024
#define C_   256
#define S_   21504
#define BNQ  (B_*NQ_)      // 8192 rows
#define BS_  (B_*S_)       // 172032 rows

// ---------------- device scratch (no allocations allowed) ----------------
__device__ float g_q   [BNQ*C_];        // shared LN output buffer (q1/q2/q3)
__device__ float g_qkv [BNQ*3*C_];
__device__ float g_attn[BNQ*C_];
__device__ float g_tgt2[BNQ*C_];
__device__ float g_tgt3[BNQ*C_];
__device__ float g_val [BS_*(size_t)C_];
__device__ float g_so  [BNQ*384];
__device__ float g_aw  [BNQ*192];
__device__ float g_ref [BNQ*2];
__device__ float g_ca  [BNQ*C_];
__device__ float g_ff1 [BNQ*1024];

// ---------------- LayerNorm: one block (256 thr) per row, C=256 ----------
__global__ void __launch_bounds__(256) ln_kernel(const float* __restrict__ x,
    const float* __restrict__ w, const float* __restrict__ b,
    float* __restrict__ y)
{
    int row = blockIdx.x;
    float v = x[(size_t)row*C_ + threadIdx.x];
    float s = v, s2 = v*v;
    __shared__ float red[16];
    int lane = threadIdx.x & 31, wid = threadIdx.x >> 5;
    #pragma unroll
    for (int o = 16; o; o >>= 1) {
        s  += __shfl_xor_sync(0xffffffffu, s,  o);
        s2 += __shfl_xor_sync(0xffffffffu, s2, o);
    }
    if (lane == 0) { red[wid] = s; red[wid+8] = s2; }
    __syncthreads();
    float ts = 0.f, ts2 = 0.f;
    #pragma unroll
    for (int i = 0; i < 8; i++) { ts += red[i]; ts2 += red[i+8]; }
    float mean = ts * (1.f/C_);
    float var  = ts2 * (1.f/C_) - mean*mean;
    float r = rsqrtf(var + 1e-5f);
    y[(size_t)row*C_ + threadIdx.x] = (v - mean)*r*w[threadIdx.x] + b[threadIdx.x];
}

// ---------------- SGEMM: C[M,N] = act(A[M,K] @ W[N,K]^T + bias) + res ----
// 128x128 block tile, BK=16, 256 threads, 8x8 per thread (split 4+4).
// M, K must be multiples of 128 / 16 (they are). N guarded.
template<int ACT>   // 0 = none, 1 = exact GELU
__global__ void __launch_bounds__(256) gemm128(const float* __restrict__ A,
    const float* __restrict__ W, const float* __restrict__ bias,
    const float* __restrict__ res, float* __restrict__ Co,
    int M, int N, int K)
{
    __shared__ float As[16][128];
    __shared__ float Bs[16][128];
    const int t  = threadIdx.x;
    const int m0 = blockIdx.y * 128, n0 = blockIdx.x * 128;
    const int lrow = t >> 2, lk = (t & 3) * 4;
    const int tx = t & 15, ty = t >> 4;

    float acc[8][8];
    #pragma unroll
    for (int i = 0; i < 8; i++)
        #pragma unroll
        for (int j = 0; j < 8; j++) acc[i][j] = 0.f;

    const float* Ap0 = A + (size_t)(m0 + lrow     ) * K + lk;
    const float* Ap1 = A + (size_t)(m0 + lrow + 64) * K + lk;
    const bool wok0 = (n0 + lrow     ) < N;
    const bool wok1 = (n0 + lrow + 64) < N;
    const float* Wp0 = W + (size_t)(n0 + lrow     ) * K + lk;
    const float* Wp1 = W + (size_t)(n0 + lrow + 64) * K + lk;

    for (int k0 = 0; k0 < K; k0 += 16) {
        float4 a0 = *(const float4*)(Ap0 + k0);
        float4 a1 = *(const float4*)(Ap1 + k0);
        float4 w0 = wok0 ? *(const float4*)(Wp0 + k0) : make_float4(0.f,0.f,0.f,0.f);
        float4 w1 = wok1 ? *(const float4*)(Wp1 + k0) : make_float4(0.f,0.f,0.f,0.f);
        __syncthreads();
        As[lk+0][lrow]    = a0.x; As[lk+1][lrow]    = a0.y; As[lk+2][lrow]    = a0.z; As[lk+3][lrow]    = a0.w;
        As[lk+0][lrow+64] = a1.x; As[lk+1][lrow+64] = a1.y; As[lk+2][lrow+64] = a1.z; As[lk+3][lrow+64] = a1.w;
        Bs[lk+0][lrow]    = w0.x; Bs[lk+1][lrow]    = w0.y; Bs[lk+2][lrow]    = w0.z; Bs[lk+3][lrow]    = w0.w;
        Bs[lk+0][lrow+64] = w1.x; Bs[lk+1][lrow+64] = w1.y; Bs[lk+2][lrow+64] = w1.z; Bs[lk+3][lrow+64] = w1.w;
        __syncthreads();
        #pragma unroll
        for (int k = 0; k < 16; k++) {
            float4 x0 = *(const float4*)&As[k][ty*4];
            float4 x1 = *(const float4*)&As[k][64 + ty*4];
            float4 y0 = *(const float4*)&Bs[k][tx*4];
            float4 y1 = *(const float4*)&Bs[k][64 + tx*4];
            float av[8] = {x0.x,x0.y,x0.z,x0.w, x1.x,x1.y,x1.z,x1.w};
            float bv[8] = {y0.x,y0.y,y0.z,y0.w, y1.x,y1.y,y1.z,y1.w};
            #pragma unroll
            for (int i = 0; i < 8; i++)
                #pragma unroll
                for (int j = 0; j < 8; j++)
                    acc[i][j] += av[i]*bv[j];
        }
    }

    #pragma unroll
    for (int i = 0; i < 8; i++) {
        int m = m0 + ((i < 4) ? (ty*4 + i) : (64 + ty*4 + i - 4));
        #pragma unroll
        for (int j = 0; j < 8; j++) {
            int n = n0 + ((j < 4) ? (tx*4 + j) : (64 + tx*4 + j - 4));
            if (n < N) {
                float v = acc[i][j] + bias[n];
                if (ACT == 1) v = 0.5f*v*(1.f + erff(v*0.70710678118654752f));
                if (res) v += res[(size_t)m*N + n];
                Co[(size_t)m*N + n] = v;
            }
        }
    }
}

// ---------------- Flash self-attention: H=8 heads, D=32, NQ=1024 ---------
// Block = (b, h, 64-query tile). 256 threads: thread t -> query r=t>>2,
// d-range g=t&3 (8 channels). Online softmax; P broadcast via shuffles.
#define SD 40   // padded smem row stride
__global__ void __launch_bounds__(256) attn_kernel(const float* __restrict__ qkv,
                                                   float* __restrict__ out)
{
    __shared__ float Qs[64][SD];
    __shared__ float Ks[64][SD];
    __shared__ float Vs[64][SD];
    const int blk = blockIdx.x;
    const int qt = blk & 15;
    const int h  = (blk >> 4) & 7;
    const int b  = blk >> 7;
    const int t  = threadIdx.x;
    const int lane = t & 31;
    const float scale = 0.17677669529663687f;   // 1/sqrt(32)

    const float* qbase = qkv + ((size_t)(b*NQ_ + qt*64))*768 + h*32;
    #pragma unroll
    for (int i = 0; i < 2; i++) {
        int id = t + i*256;                 // float4 id 0..511
        int row = id >> 3, c4 = (id & 7)*4;
        float4 v = *(const float4*)(qbase + (size_t)row*768 + c4);
        v.x *= scale; v.y *= scale; v.z *= scale; v.w *= scale;
        *(float4*)&Qs[row][c4] = v;
    }
    const int r = t >> 2, g = t & 3;
    const float* kbase = qkv + (size_t)(b*NQ_)*768 + 256 + h*32;
    const float* vbase = qkv + (size_t)(b*NQ_)*768 + 512 + h*32;

    float m = -1e30f, l = 0.f;
    float o[8] = {0,0,0,0,0,0,0,0};

    for (int kt = 0; kt < 16; kt++) {
        __syncthreads();
        #pragma unroll
        for (int i = 0; i < 2; i++) {
            int id = t + i*256;
            int row = id >> 3, c4 = (id & 7)*4;
            *(float4*)&Ks[row][c4] = *(const float4*)(kbase + (size_t)(kt*64+row)*768 + c4);
            *(float4*)&Vs[row][c4] = *(const float4*)(vbase + (size_t)(kt*64+row)*768 + c4);
        }
        __syncthreads();

        float s[16];
        #pragma unroll
        for (int kk = 0; kk < 16; kk++) {
            int k2 = kk*4 + g;
            float a = 0.f;
            #pragma unroll
            for (int d4 = 0; d4 < 8; d4++) {
                float4 qv = *(const float4*)&Qs[r][d4*4];
                float4 kv = *(const float4*)&Ks[k2][d4*4];
                a += qv.x*kv.x + qv.y*kv.y + qv.z*kv.z + qv.w*kv.w;
            }
            s[kk] = a;
        }
        float mloc = s[0];
        #pragma unroll
        for (int kk = 1; kk < 16; kk++) mloc = fmaxf(mloc, s[kk]);
        mloc = fmaxf(mloc, __shfl_xor_sync(0xffffffffu, mloc, 1));
        mloc = fmaxf(mloc, __shfl_xor_sync(0xffffffffu, mloc, 2));
        float mnew = fmaxf(m, mloc);
        float corr = __expf(m - mnew);
        float lsum = 0.f;
        #pragma unroll
        for (int kk = 0; kk < 16; kk++) { s[kk] = __expf(s[kk]-mnew); lsum += s[kk]; }
        lsum += __shfl_xor_sync(0xffffffffu, lsum, 1);
        lsum += __shfl_xor_sync(0xffffffffu, lsum, 2);
        l = l*corr + lsum;
        m = mnew;
        #pragma unroll
        for (int j = 0; j < 8; j++) o[j] *= corr;

        const int base_lane = lane & ~3;
        #pragma unroll
        for (int kk = 0; kk < 16; kk++) {
            #pragma unroll
            for (int g2 = 0; g2 < 4; g2++) {
                float p = __shfl_sync(0xffffffffu, s[kk], base_lane + g2);
                int k2 = kk*4 + g2;
                float4 v0 = *(const float4*)&Vs[k2][g*8];
                float4 v1 = *(const float4*)&Vs[k2][g*8+4];
                o[0] += p*v0.x; o[1] += p*v0.y; o[2] += p*v0.z; o[3] += p*v0.w;
                o[4] += p*v1.x; o[5] += p*v1.y; o[6] += p*v1.z; o[7] += p*v1.w;
            }
        }
    }
    float inv = 1.f / l;
    float* ob = out + ((size_t)(b*NQ_ + qt*64 + r))*C_ + h*32 + g*8;
    #pragma unroll
    for (int j = 0; j < 8; j++) ob[j] = o[j]*inv;
}

// ---------------- reference points: sigmoid(q @ ref_w^T + ref_b) ---------
__global__ void __launch_bounds__(256) ref_kernel(const float* __restrict__ q,
    const float* __restrict__ rw, const float* __restrict__ rb,
    float* __restrict__ outp)
{
    int wid = threadIdx.x >> 5, lane = threadIdx.x & 31;
    int row = blockIdx.x*8 + wid;
    const float* x = q + (size_t)row*C_;
    float s0 = 0.f, s1 = 0.f;
    #pragma unroll
    for (int i = 0; i < 8; i++) {
        float xv = x[lane + 32*i];
        s0 += xv * rw[lane + 32*i];
        s1 += xv * rw[C_ + lane + 32*i];
    }
    #pragma unroll
    for (int o = 16; o; o >>= 1) {
        s0 += __shfl_xor_sync(0xffffffffu, s0, o);
        s1 += __shfl_xor_sync(0xffffffffu, s1, o);
    }
    if (lane == 0) {
        outp[(size_t)row*2    ] = 1.f/(1.f + __expf(-(s0 + rb[0])));
        outp[(size_t)row*2 + 1] = 1.f/(1.f + __expf(-(s1 + rb[1])));
    }
}

// ---------------- MSDeformAttn sampling: warp per (b,q,h), lane = channel -
__global__ void __launch_bounds__(256) msdeform_kernel(const float* __restrict__ value,
    const float* __restrict__ ref, const float* __restrict__ so,
    const float* __restrict__ aw, float* __restrict__ outp)
{
    const int wid = threadIdx.x >> 5, lane = threadIdx.x & 31;
    const int gw = blockIdx.x*8 + wid;      // ((b*NQ+q)*8 + h)
    const int h  = gw & 7;
    const int bq = gw >> 3;
    const int b  = bq >> 10;

    // softmax over 24 attention-weight logits (lanes 0..23)
    float logit = -1e30f;
    if (lane < 24) logit = aw[(size_t)bq*192 + h*24 + lane];
    float mx = logit;
    #pragma unroll
    for (int o = 16; o; o >>= 1) mx = fmaxf(mx, __shfl_xor_sync(0xffffffffu, mx, o));
    float e = (lane < 24) ? __expf(logit - mx) : 0.f;
    float ssum = e;
    #pragma unroll
    for (int o = 16; o; o >>= 1) ssum += __shfl_xor_sync(0xffffffffu, ssum, o);
    float pw = e / ssum;

    // sampling offsets (lanes 0..23 hold their own point)
    float offx = 0.f, offy = 0.f;
    if (lane < 24) {
        int l = lane >> 3, p = lane & 7;
        const float* sp = so + (size_t)bq*384 + ((size_t)((h*3 + l)*8 + p))*2;
        offx = sp[0]; offy = sp[1];
    }
    float rx = ref[(size_t)bq*2], ry = ref[(size_t)bq*2 + 1];

    const int HL[3] = {128, 64, 32};
    const int WL[3] = {128, 64, 32};
    const int ST[3] = {0, 16384, 20480};

    float acc = 0.f;
    #pragma unroll
    for (int l = 0; l < 3; l++) {
        const int h_l = HL[l], w_l = WL[l], start = ST[l];
        const float gxb = rx * (float)w_l - 0.5f;
        const float gyb = ry * (float)h_l - 0.5f;
        const float* vb = value + ((size_t)(b*S_ + start))*C_ + h*32 + lane;
        #pragma unroll
        for (int p = 0; p < 8; p++) {
            int lp = l*8 + p;
            float ox = __shfl_sync(0xffffffffu, offx, lp);
            float oy = __shfl_sync(0xffffffffu, offy, lp);
            float w  = __shfl_sync(0xffffffffu, pw,   lp);
            float gx = gxb + ox;
            float gy = gyb + oy;
            float x0f = floorf(gx), y0f = floorf(gy);
            float lx = gx - x0f, ly = gy - y0f;
            int x0 = (int)x0f, y0 = (int)y0f;
            float w00 = (1.f-lx)*(1.f-ly)*w;
            float w01 = lx*(1.f-ly)*w;
            float w10 = (1.f-lx)*ly*w;
            float w11 = lx*ly*w;
            bool vx0 = (x0   >= 0) & (x0   < w_l);
            bool vx1 = (x0+1 >= 0) & (x0+1 < w_l);
            if (y0 >= 0 && y0 < h_l) {
                const float* rowp = vb + (size_t)y0*w_l*C_;
                if (vx0) acc += w00 * rowp[(size_t)x0*C_];
                if (vx1) acc += w01 * rowp[(size_t)(x0+1)*C_];
            }
            if (y0+1 >= 0 && y0+1 < h_l) {
                const float* rowp = vb + (size_t)(y0+1)*w_l*C_;
                if (vx0) acc += w10 * rowp[(size_t)x0*C_];
                if (vx1) acc += w11 * rowp[(size_t)(x0+1)*C_];
            }
        }
    }
    outp[(size_t)bq*C_ + h*32 + lane] = acc;
}

// ---------------- launch ----------------
extern "C" void kernel_launch(void* const* d_in, const int* in_sizes, int n_in,
                              void* d_out, int out_size)
{
    const float* tgt    = (const float*)d_in[0];
    const float* memory = (const float*)d_in[1];
    const float* n1w = (const float*)d_in[2];
    const float* n1b = (const float*)d_in[3];
    const float* inw = (const float*)d_in[4];
    const float* inb = (const float*)d_in[5];
    const float* outw= (const float*)d_in[6];
    const float* outb= (const float*)d_in[7];
    const float* n2w = (const float*)d_in[8];
    const float* n2b = (const float*)d_in[9];
    const float* refw= (const float*)d_in[10];
    const float* refb= (const float*)d_in[11];
    const float* sow = (const float*)d_in[12];
    const float* sob = (const float*)d_in[13];
    const float* aww = (const float*)d_in[14];
    const float* awb = (const float*)d_in[15];
    const float* vpw = (const float*)d_in[16];
    const float* vpb = (const float*)d_in[17];
    const float* opw = (const float*)d_in[18];
    const float* opb = (const float*)d_in[19];
    const float* n3w = (const float*)d_in[20];
    const float* n3b = (const float*)d_in[21];
    const float* l1w = (const float*)d_in[22];
    const float* l1b = (const float*)d_in[23];
    const float* l2w = (const float*)d_in[24];
    const float* l2b = (const float*)d_in[25];

    float *q, *qkv, *attn, *tgt2, *tgt3, *val, *so, *aw, *refo, *ca, *ff1;
    cudaGetSymbolAddress((void**)&q,    g_q);
    cudaGetSymbolAddress((void**)&qkv,  g_qkv);
    cudaGetSymbolAddress((void**)&attn, g_attn);
    cudaGetSymbolAddress((void**)&tgt2, g_tgt2);
    cudaGetSymbolAddress((void**)&tgt3, g_tgt3);
    cudaGetSymbolAddress((void**)&val,  g_val);
    cudaGetSymbolAddress((void**)&so,   g_so);
    cudaGetSymbolAddress((void**)&aw,   g_aw);
    cudaGetSymbolAddress((void**)&refo, g_ref);
    cudaGetSymbolAddress((void**)&ca,   g_ca);
    cudaGetSymbolAddress((void**)&ff1,  g_ff1);

    // 1. q1 = LN(tgt)
    ln_kernel<<<BNQ, 256>>>(tgt, n1w, n1b, q);
    // 2. qkv = q1 @ in_w^T + in_b
    gemm128<0><<<dim3(768/128, BNQ/128), 256>>>(q, inw, inb, nullptr, qkv, BNQ, 768, C_);
    // 3. self-attention
    attn_kernel<<<B_*8*16, 256>>>(qkv, attn);
    // 4. tgt2 = tgt + attn @ out_w^T + out_b
    gemm128<0><<<dim3(C_/128, BNQ/128), 256>>>(attn, outw, outb, tgt, tgt2, BNQ, C_, C_);
    // 5. q2 = LN(tgt2)
    ln_kernel<<<BNQ, 256>>>(tgt2, n2w, n2b, q);
    // 6. value = memory @ vp_w^T + vp_b (the big one)
    gemm128<0><<<dim3(C_/128, BS_/128), 256>>>(memory, vpw, vpb, nullptr, val, BS_, C_, C_);
    // 7. sampling offsets
    gemm128<0><<<dim3(3, BNQ/128), 256>>>(q, sow, sob, nullptr, so, BNQ, 384, C_);
    // 8. attention weight logits (N=192, guarded)
    gemm128<0><<<dim3(2, BNQ/128), 256>>>(q, aww, awb, nullptr, aw, BNQ, 192, C_);
    // 9. reference points
    ref_kernel<<<BNQ/8, 256>>>(q, refw, refb, refo);
    // 10. deformable sampling
    msdeform_kernel<<<BNQ, 256>>>(val, refo, so, aw, ca);
    // 11. tgt3 = tgt2 + ca @ op_w^T + op_b
    gemm128<0><<<dim3(C_/128, BNQ/128), 256>>>(ca, opw, opb, tgt2, tgt3, BNQ, C_, C_);
    // 12. q3 = LN(tgt3)
    ln_kernel<<<BNQ, 256>>>(tgt3, n3w, n3b, q);
    // 13. ff1 = gelu(q3 @ l1_w^T + l1_b)
    gemm128<1><<<dim3(1024/128, BNQ/128), 256>>>(q, l1w, l1b, nullptr, ff1, BNQ, 1024, C_);
    // 14. out = tgt3 + ff1 @ l2_w^T + l2_b
    gemm128<0><<<dim3(C_/128, BNQ/128), 256>>>(ff1, l2w, l2b, tgt3, (float*)d_out, BNQ, C_, 1024);
}

// round 2
// speedup vs baseline: 1.6228x; 1.6228x over previous
#include <cuda_runtime.h>
#include <math.h>

// Problem constants
#define B_   8
#define NQ_  1024
#define C_   256
#define S_   21504
#define BNQ  (B_*NQ_)      // 8192 rows
#define BS_  (B_*S_)       // 172032 rows

// ---------------- device scratch (no allocations allowed) ----------------
__device__ float g_q   [BNQ*C_];        // shared LN output buffer (q1/q2/q3)
__device__ float g_qkv [BNQ*3*C_];
__device__ float g_attn[BNQ*C_];
__device__ float g_tgt2[BNQ*C_];
__device__ float g_tgt3[BNQ*C_];
__device__ float g_val [BS_*(size_t)C_];
__device__ float g_so  [BNQ*384];
__device__ float g_aw  [BNQ*192];
__device__ float g_ref [BNQ*2];
__device__ float g_ca  [BNQ*C_];
__device__ float g_ff1 [BNQ*1024];

// ---------------- LayerNorm: one block (256 thr) per row, C=256 ----------
__global__ void __launch_bounds__(256) ln_kernel(const float* __restrict__ x,
    const float* __restrict__ w, const float* __restrict__ b,
    float* __restrict__ y)
{
    int row = blockIdx.x;
    float v = x[(size_t)row*C_ + threadIdx.x];
    float s = v, s2 = v*v;
    __shared__ float red[16];
    int lane = threadIdx.x & 31, wid = threadIdx.x >> 5;
    #pragma unroll
    for (int o = 16; o; o >>= 1) {
        s  += __shfl_xor_sync(0xffffffffu, s,  o);
        s2 += __shfl_xor_sync(0xffffffffu, s2, o);
    }
    if (lane == 0) { red[wid] = s; red[wid+8] = s2; }
    __syncthreads();
    float ts = 0.f, ts2 = 0.f;
    #pragma unroll
    for (int i = 0; i < 8; i++) { ts += red[i]; ts2 += red[i+8]; }
    float mean = ts * (1.f/C_);
    float var  = ts2 * (1.f/C_) - mean*mean;
    float r = rsqrtf(var + 1e-5f);
    y[(size_t)row*C_ + threadIdx.x] = (v - mean)*r*w[threadIdx.x] + b[threadIdx.x];
}

// ---------------- TF32 tensor-core GEMM -----------------------------------
// C[M,N] = act(A[M,K] @ W[N,K]^T + bias) (+ res)
// 128x128 block tile, BK=16, 256 threads (8 warps, 2x4), warp tile 64x32.
// mma.sync.m16n8k8 tf32. Double-buffered smem, pad-20 rows (conflict-free).
// Requires: M % 128 == 0, K % 16 == 0. N guarded.

__device__ __forceinline__ unsigned cvt_tf32(float f) {
    unsigned r;
    asm("cvt.rna.tf32.f32 %0, %1;" : "=r"(r) : "f"(f));
    return r;
}
__device__ __forceinline__ uint4 cvt4_tf32(float4 v) {
    uint4 u;
    u.x = cvt_tf32(v.x); u.y = cvt_tf32(v.y);
    u.z = cvt_tf32(v.z); u.w = cvt_tf32(v.w);
    return u;
}
__device__ __forceinline__ void mma_tf32(float* d, const unsigned* a, const unsigned* b) {
    asm volatile(
      "mma.sync.aligned.m16n8k8.row.col.f32.tf32.tf32.f32 "
      "{%0,%1,%2,%3}, {%4,%5,%6,%7}, {%8,%9}, {%0,%1,%2,%3};\n"
      : "+f"(d[0]), "+f"(d[1]), "+f"(d[2]), "+f"(d[3])
      : "r"(a[0]), "r"(a[1]), "r"(a[2]), "r"(a[3]), "r"(b[0]), "r"(b[1]));
}

template<int ACT>   // 0 = none, 1 = exact GELU
__global__ void __launch_bounds__(256) gemm_tc(const float* __restrict__ A,
    const float* __restrict__ W, const float* __restrict__ bias,
    const float* __restrict__ res, float* __restrict__ Co,
    int M, int N, int K)
{
    __shared__ unsigned As[2][128][20];
    __shared__ unsigned Bs[2][128][20];

    const int t    = threadIdx.x;
    const int warp = t >> 5;
    const int lane = t & 31;
    const int grp  = lane >> 2;      // 0..7
    const int t4   = lane & 3;       // 0..3
    const int wm   = warp & 1;       // 2 warp-rows of 64
    const int wn   = warp >> 1;      // 4 warp-cols of 32
    const int m0   = blockIdx.y * 128, n0 = blockIdx.x * 128;

    const int lrow = t >> 2;         // 0..63 (load row)
    const int lc4  = (t & 3) * 4;    // 0,4,8,12 (k offset)

    const float* Ag0 = A + (size_t)(m0 + lrow     ) * K + lc4;
    const float* Ag1 = A + (size_t)(m0 + lrow + 64) * K + lc4;
    const bool wok0 = (n0 + lrow     ) < N;
    const bool wok1 = (n0 + lrow + 64) < N;
    const float* Wg0 = W + (size_t)(n0 + lrow     ) * K + lc4;
    const float* Wg1 = W + (size_t)(n0 + lrow + 64) * K + lc4;

    float acc[4][4][4];
    #pragma unroll
    for (int i = 0; i < 4; i++)
        #pragma unroll
        for (int j = 0; j < 4; j++)
            #pragma unroll
            for (int r = 0; r < 4; r++) acc[i][j][r] = 0.f;

    const float4 z4 = make_float4(0.f,0.f,0.f,0.f);

    // preload tile k0=0 into smem stage 0
    {
        float4 a0 = *(const float4*)Ag0;
        float4 a1 = *(const float4*)Ag1;
        float4 b0 = wok0 ? *(const float4*)Wg0 : z4;
        float4 b1 = wok1 ? *(const float4*)Wg1 : z4;
        *(uint4*)&As[0][lrow   ][lc4] = cvt4_tf32(a0);
        *(uint4*)&As[0][lrow+64][lc4] = cvt4_tf32(a1);
        *(uint4*)&Bs[0][lrow   ][lc4] = cvt4_tf32(b0);
        *(uint4*)&Bs[0][lrow+64][lc4] = cvt4_tf32(b1);
    }
    __syncthreads();

    const int iters = K >> 4;
    for (int it = 0; it < iters; it++) {
        const int s = it & 1;
        float4 a0, a1, b0, b1;
        const bool more = (it + 1) < iters;
        if (more) {
            int ko = (it + 1) << 4;
            a0 = *(const float4*)(Ag0 + ko);
            a1 = *(const float4*)(Ag1 + ko);
            b0 = wok0 ? *(const float4*)(Wg0 + ko) : z4;
            b1 = wok1 ? *(const float4*)(Wg1 + ko) : z4;
        }

        #pragma unroll
        for (int kb = 0; kb < 16; kb += 8) {
            unsigned af[4][4], bf[4][2];
            #pragma unroll
            for (int mt = 0; mt < 4; mt++) {
                int m = wm*64 + mt*16 + grp;
                af[mt][0] = As[s][m  ][kb + t4];
                af[mt][1] = As[s][m+8][kb + t4];
                af[mt][2] = As[s][m  ][kb + t4 + 4];
                af[mt][3] = As[s][m+8][kb + t4 + 4];
            }
            #pragma unroll
            for (int nt = 0; nt < 4; nt++) {
                int n = wn*32 + nt*8 + grp;
                bf[nt][0] = Bs[s][n][kb + t4];
                bf[nt][1] = Bs[s][n][kb + t4 + 4];
            }
            #pragma unroll
            for (int mt = 0; mt < 4; mt++)
                #pragma unroll
                for (int nt = 0; nt < 4; nt++)
                    mma_tf32(acc[mt][nt], af[mt], bf[nt]);
        }

        if (more) {
            const int sn = s ^ 1;
            *(uint4*)&As[sn][lrow   ][lc4] = cvt4_tf32(a0);
            *(uint4*)&As[sn][lrow+64][lc4] = cvt4_tf32(a1);
            *(uint4*)&Bs[sn][lrow   ][lc4] = cvt4_tf32(b0);
            *(uint4*)&Bs[sn][lrow+64][lc4] = cvt4_tf32(b1);
        }
        __syncthreads();
    }

    // epilogue: c0 (grp, t4*2), c1 (grp, t4*2+1), c2 (grp+8, t4*2), c3 (grp+8, t4*2+1)
    #pragma unroll
    for (int mt = 0; mt < 4; mt++) {
        #pragma unroll
        for (int nt = 0; nt < 4; nt++) {
            int rbase = m0 + wm*64 + mt*16 + grp;
            int cbase = n0 + wn*32 + nt*8 + t4*2;
            #pragma unroll
            for (int rr = 0; rr < 2; rr++) {
                int m = rbase + rr*8;
                #pragma unroll
                for (int cc = 0; cc < 2; cc++) {
                    int n = cbase + cc;
                    if (n < N) {
                        float v = acc[mt][nt][rr*2 + cc] + bias[n];
                        if (ACT == 1) v = 0.5f*v*(1.f + erff(v*0.70710678118654752f));
                        if (res) v += res[(size_t)m*N + n];
                        Co[(size_t)m*N + n] = v;
                    }
                }
            }
        }
    }
}

// ---------------- Flash self-attention: H=8 heads, D=32, NQ=1024 ---------
#define SD 40   // padded smem row stride
__global__ void __launch_bounds__(256) attn_kernel(const float* __restrict__ qkv,
                                                   float* __restrict__ out)
{
    __shared__ float Qs[64][SD];
    __shared__ float Ks[64][SD];
    __shared__ float Vs[64][SD];
    const int blk = blockIdx.x;
    const int qt = blk & 15;
    const int h  = (blk >> 4) & 7;
    const int b  = blk >> 7;
    const int t  = threadIdx.x;
    const int lane = t & 31;
    const float scale = 0.17677669529663687f;   // 1/sqrt(32)

    const float* qbase = qkv + ((size_t)(b*NQ_ + qt*64))*768 + h*32;
    #pragma unroll
    for (int i = 0; i < 2; i++) {
        int id = t + i*256;                 // float4 id 0..511
        int row = id >> 3, c4 = (id & 7)*4;
        float4 v = *(const float4*)(qbase + (size_t)row*768 + c4);
        v.x *= scale; v.y *= scale; v.z *= scale; v.w *= scale;
        *(float4*)&Qs[row][c4] = v;
    }
    const int r = t >> 2, g = t & 3;
    const float* kbase = qkv + (size_t)(b*NQ_)*768 + 256 + h*32;
    const float* vbase = qkv + (size_t)(b*NQ_)*768 + 512 + h*32;

    float m = -1e30f, l = 0.f;
    float o[8] = {0,0,0,0,0,0,0,0};

    for (int kt = 0; kt < 16; kt++) {
        __syncthreads();
        #pragma unroll
        for (int i = 0; i < 2; i++) {
            int id = t + i*256;
            int row = id >> 3, c4 = (id & 7)*4;
            *(float4*)&Ks[row][c4] = *(const float4*)(kbase + (size_t)(kt*64+row)*768 + c4);
            *(float4*)&Vs[row][c4] = *(const float4*)(vbase + (size_t)(kt*64+row)*768 + c4);
        }
        __syncthreads();

        float s[16];
        #pragma unroll
        for (int kk = 0; kk < 16; kk++) {
            int k2 = kk*4 + g;
            float a = 0.f;
            #pragma unroll
            for (int d4 = 0; d4 < 8; d4++) {
                float4 qv = *(const float4*)&Qs[r][d4*4];
                float4 kv = *(const float4*)&Ks[k2][d4*4];
                a += qv.x*kv.x + qv.y*kv.y + qv.z*kv.z + qv.w*kv.w;
            }
            s[kk] = a;
        }
        float mloc = s[0];
        #pragma unroll
        for (int kk = 1; kk < 16; kk++) mloc = fmaxf(mloc, s[kk]);
        mloc = fmaxf(mloc, __shfl_xor_sync(0xffffffffu, mloc, 1));
        mloc = fmaxf(mloc, __shfl_xor_sync(0xffffffffu, mloc, 2));
        float mnew = fmaxf(m, mloc);
        float corr = __expf(m - mnew);
        float lsum = 0.f;
        #pragma unroll
        for (int kk = 0; kk < 16; kk++) { s[kk] = __expf(s[kk]-mnew); lsum += s[kk]; }
        lsum += __shfl_xor_sync(0xffffffffu, lsum, 1);
        lsum += __shfl_xor_sync(0xffffffffu, lsum, 2);
        l = l*corr + lsum;
        m = mnew;
        #pragma unroll
        for (int j = 0; j < 8; j++) o[j] *= corr;

        const int base_lane = lane & ~3;
        #pragma unroll
        for (int kk = 0; kk < 16; kk++) {
            #pragma unroll
            for (int g2 = 0; g2 < 4; g2++) {
                float p = __shfl_sync(0xffffffffu, s[kk], base_lane + g2);
                int k2 = kk*4 + g2;
                float4 v0 = *(const float4*)&Vs[k2][g*8];
                float4 v1 = *(const float4*)&Vs[k2][g*8+4];
                o[0] += p*v0.x; o[1] += p*v0.y; o[2] += p*v0.z; o[3] += p*v0.w;
                o[4] += p*v1.x; o[5] += p*v1.y; o[6] += p*v1.z; o[7] += p*v1.w;
            }
        }
    }
    float inv = 1.f / l;
    float* ob = out + ((size_t)(b*NQ_ + qt*64 + r))*C_ + h*32 + g*8;
    #pragma unroll
    for (int j = 0; j < 8; j++) ob[j] = o[j]*inv;
}

// ---------------- reference points: sigmoid(q @ ref_w^T + ref_b) ---------
__global__ void __launch_bounds__(256) ref_kernel(const float* __restrict__ q,
    const float* __restrict__ rw, const float* __restrict__ rb,
    float* __restrict__ outp)
{
    int wid = threadIdx.x >> 5, lane = threadIdx.x & 31;
    int row = blockIdx.x*8 + wid;
    const float* x = q + (size_t)row*C_;
    float s0 = 0.f, s1 = 0.f;
    #pragma unroll
    for (int i = 0; i < 8; i++) {
        float xv = x[lane + 32*i];
        s0 += xv * rw[lane + 32*i];
        s1 += xv * rw[C_ + lane + 32*i];
    }
    #pragma unroll
    for (int o = 16; o; o >>= 1) {
        s0 += __shfl_xor_sync(0xffffffffu, s0, o);
        s1 += __shfl_xor_sync(0xffffffffu, s1, o);
    }
    if (lane == 0) {
        outp[(size_t)row*2    ] = 1.f/(1.f + __expf(-(s0 + rb[0])));
        outp[(size_t)row*2 + 1] = 1.f/(1.f + __expf(-(s1 + rb[1])));
    }
}

// ---------------- MSDeformAttn sampling: warp per (b,q,h), lane = channel -
__global__ void __launch_bounds__(256) msdeform_kernel(const float* __restrict__ value,
    const float* __restrict__ ref, const float* __restrict__ so,
    const float* __restrict__ aw, float* __restrict__ outp)
{
    const int wid = threadIdx.x >> 5, lane = threadIdx.x & 31;
    const int gw = blockIdx.x*8 + wid;      // ((b*NQ+q)*8 + h)
    const int h  = gw & 7;
    const int bq = gw >> 3;
    const int b  = bq >> 10;

    // softmax over 24 attention-weight logits (lanes 0..23)
    float logit = -1e30f;
    if (lane < 24) logit = aw[(size_t)bq*192 + h*24 + lane];
    float mx = logit;
    #pragma unroll
    for (int o = 16; o; o >>= 1) mx = fmaxf(mx, __shfl_xor_sync(0xffffffffu, mx, o));
    float e = (lane < 24) ? __expf(logit - mx) : 0.f;
    float ssum = e;
    #pragma unroll
    for (int o = 16; o; o >>= 1) ssum += __shfl_xor_sync(0xffffffffu, ssum, o);
    float pw = e / ssum;

    // sampling offsets (lanes 0..23 hold their own point)
    float offx = 0.f, offy = 0.f;
    if (lane < 24) {
        int l = lane >> 3, p = lane & 7;
        const float* sp = so + (size_t)bq*384 + ((size_t)((h*3 + l)*8 + p))*2;
        offx = sp[0]; offy = sp[1];
    }
    float rx = ref[(size_t)bq*2], ry = ref[(size_t)bq*2 + 1];

    const int HL[3] = {128, 64, 32};
    const int WL[3] = {128, 64, 32};
    const int ST[3] = {0, 16384, 20480};

    float acc = 0.f;
    #pragma unroll
    for (int l = 0; l < 3; l++) {
        const int h_l = HL[l], w_l = WL[l], start = ST[l];
        const float gxb = rx * (float)w_l - 0.5f;
        const float gyb = ry * (float)h_l - 0.5f;
        const float* vb = value + ((size_t)(b*S_ + start))*C_ + h*32 + lane;
        #pragma unroll
        for (int p = 0; p < 8; p++) {
            int lp = l*8 + p;
            float ox = __shfl_sync(0xffffffffu, offx, lp);
            float oy = __shfl_sync(0xffffffffu, offy, lp);
            float w  = __shfl_sync(0xffffffffu, pw,   lp);
            float gx = gxb + ox;
            float gy = gyb + oy;
            float x0f = floorf(gx), y0f = floorf(gy);
            float lx = gx - x0f, ly = gy - y0f;
            int x0 = (int)x0f, y0 = (int)y0f;
            float w00 = (1.f-lx)*(1.f-ly)*w;
            float w01 = lx*(1.f-ly)*w;
            float w10 = (1.f-lx)*ly*w;
            float w11 = lx*ly*w;
            bool vx0 = (x0   >= 0) & (x0   < w_l);
            bool vx1 = (x0+1 >= 0) & (x0+1 < w_l);
            if (y0 >= 0 && y0 < h_l) {
                const float* rowp = vb + (size_t)y0*w_l*C_;
                if (vx0) acc += w00 * rowp[(size_t)x0*C_];
                if (vx1) acc += w01 * rowp[(size_t)(x0+1)*C_];
            }
            if (y0+1 >= 0 && y0+1 < h_l) {
                const float* rowp = vb + (size_t)(y0+1)*w_l*C_;
                if (vx0) acc += w10 * rowp[(size_t)x0*C_];
                if (vx1) acc += w11 * rowp[(size_t)(x0+1)*C_];
            }
        }
    }
    outp[(size_t)bq*C_ + h*32 + lane] = acc;
}

// ---------------- launch ----------------
extern "C" void kernel_launch(void* const* d_in, const int* in_sizes, int n_in,
                              void* d_out, int out_size)
{
    const float* tgt    = (const float*)d_in[0];
    const float* memory = (const float*)d_in[1];
    const float* n1w = (const float*)d_in[2];
    const float* n1b = (const float*)d_in[3];
    const float* inw = (const float*)d_in[4];
    const float* inb = (const float*)d_in[5];
    const float* outw= (const float*)d_in[6];
    const float* outb= (const float*)d_in[7];
    const float* n2w = (const float*)d_in[8];
    const float* n2b = (const float*)d_in[9];
    const float* refw= (const float*)d_in[10];
    const float* refb= (const float*)d_in[11];
    const float* sow = (const float*)d_in[12];
    const float* sob = (const float*)d_in[13];
    const float* aww = (const float*)d_in[14];
    const float* awb = (const float*)d_in[15];
    const float* vpw = (const float*)d_in[16];
    const float* vpb = (const float*)d_in[17];
    const float* opw = (const float*)d_in[18];
    const float* opb = (const float*)d_in[19];
    const float* n3w = (const float*)d_in[20];
    const float* n3b = (const float*)d_in[21];
    const float* l1w = (const float*)d_in[22];
    const float* l1b = (const float*)d_in[23];
    const float* l2w = (const float*)d_in[24];
    const float* l2b = (const float*)d_in[25];

    float *q, *qkv, *attn, *tgt2, *tgt3, *val, *so, *aw, *refo, *ca, *ff1;
    cudaGetSymbolAddress((void**)&q,    g_q);
    cudaGetSymbolAddress((void**)&qkv,  g_qkv);
    cudaGetSymbolAddress((void**)&attn, g_attn);
    cudaGetSymbolAddress((void**)&tgt2, g_tgt2);
    cudaGetSymbolAddress((void**)&tgt3, g_tgt3);
    cudaGetSymbolAddress((void**)&val,  g_val);
    cudaGetSymbolAddress((void**)&so,   g_so);
    cudaGetSymbolAddress((void**)&aw,   g_aw);
    cudaGetSymbolAddress((void**)&refo, g_ref);
    cudaGetSymbolAddress((void**)&ca,   g_ca);
    cudaGetSymbolAddress((void**)&ff1,  g_ff1);

    // 1. q1 = LN(tgt)
    ln_kernel<<<BNQ, 256>>>(tgt, n1w, n1b, q);
    // 2. qkv = q1 @ in_w^T + in_b
    gemm_tc<0><<<dim3(768/128, BNQ/128), 256>>>(q, inw, inb, nullptr, qkv, BNQ, 768, C_);
    // 3. self-attention
    attn_kernel<<<B_*8*16, 256>>>(qkv, attn);
    // 4. tgt2 = tgt + attn @ out_w^T + out_b
    gemm_tc<0><<<dim3(C_/128, BNQ/128), 256>>>(attn, outw, outb, tgt, tgt2, BNQ, C_, C_);
    // 5. q2 = LN(tgt2)
    ln_kernel<<<BNQ, 256>>>(tgt2, n2w, n2b, q);
    // 6. value = memory @ vp_w^T + vp_b (the big one)
    gemm_tc<0><<<dim3(C_/128, BS_/128), 256>>>(memory, vpw, vpb, nullptr, val, BS_, C_, C_);
    // 7. sampling offsets
    gemm_tc<0><<<dim3(3, BNQ/128), 256>>>(q, sow, sob, nullptr, so, BNQ, 384, C_);
    // 8. attention weight logits (N=192, guarded)
    gemm_tc<0><<<dim3(2, BNQ/128), 256>>>(q, aww, awb, nullptr, aw, BNQ, 192, C_);
    // 9. reference points
    ref_kernel<<<BNQ/8, 256>>>(q, refw, refb, refo);
    // 10. deformable sampling
    msdeform_kernel<<<BNQ, 256>>>(val, refo, so, aw, ca);
    // 11. tgt3 = tgt2 + ca @ op_w^T + op_b
    gemm_tc<0><<<dim3(C_/128, BNQ/128), 256>>>(ca, opw, opb, tgt2, tgt3, BNQ, C_, C_);
    // 12. q3 = LN(tgt3)
    ln_kernel<<<BNQ, 256>>>(tgt3, n3w, n3b, q);
    // 13. ff1 = gelu(q3 @ l1_w^T + l1_b)
    gemm_tc<1><<<dim3(1024/128, BNQ/128), 256>>>(q, l1w, l1b, nullptr, ff1, BNQ, 1024, C_);
    // 14. out = tgt3 + ff1 @ l2_w^T + l2_b
    gemm_tc<0><<<dim3(C_/128, BNQ/128), 256>>>(ff1, l2w, l2b, tgt3, (float*)d_out, BNQ, C_, 1024);
}

// round 3
// speedup vs baseline: 1.7970x; 1.1074x over previous
#include <cuda_runtime.h>
#include <math.h>

// Problem constants
#define B_   8
#define NQ_  1024
#define C_   256
#define S_   21504
#define BNQ  (B_*NQ_)      // 8192 rows
#define BS_  (B_*S_)       // 172032 rows

// ---------------- device scratch (no allocations allowed) ----------------
__device__ float g_q   [BNQ*C_];        // shared LN output buffer (q1/q2/q3)
__device__ float g_qkv [BNQ*3*C_];
__device__ float g_attn[BNQ*C_];
__device__ float g_tgt2[BNQ*C_];
__device__ float g_tgt3[BNQ*C_];
__device__ float g_val [BS_*(size_t)C_];
__device__ float g_so  [BNQ*384];
__device__ float g_aw  [BNQ*192];
__device__ float g_ref [BNQ*2];
__device__ float g_ca  [BNQ*C_];
__device__ float g_ff1 [BNQ*1024];

// ---------------- LayerNorm: one block (256 thr) per row, C=256 ----------
__global__ void __launch_bounds__(256) ln_kernel(const float* __restrict__ x,
    const float* __restrict__ w, const float* __restrict__ b,
    float* __restrict__ y)
{
    int row = blockIdx.x;
    float v = x[(size_t)row*C_ + threadIdx.x];
    float s = v, s2 = v*v;
    __shared__ float red[16];
    int lane = threadIdx.x & 31, wid = threadIdx.x >> 5;
    #pragma unroll
    for (int o = 16; o; o >>= 1) {
        s  += __shfl_xor_sync(0xffffffffu, s,  o);
        s2 += __shfl_xor_sync(0xffffffffu, s2, o);
    }
    if (lane == 0) { red[wid] = s; red[wid+8] = s2; }
    __syncthreads();
    float ts = 0.f, ts2 = 0.f;
    #pragma unroll
    for (int i = 0; i < 8; i++) { ts += red[i]; ts2 += red[i+8]; }
    float mean = ts * (1.f/C_);
    float var  = ts2 * (1.f/C_) - mean*mean;
    float r = rsqrtf(var + 1e-5f);
    y[(size_t)row*C_ + threadIdx.x] = (v - mean)*r*w[threadIdx.x] + b[threadIdx.x];
}

// ---------------- TF32 tensor-core GEMM (cp.async 3-stage) ---------------
// C[M,N] = act(A[M,K] @ W[N,K]^T + bias) (+ res)
// 128x128 block tile, BK=16, 256 threads (8 warps 2x4), warp tile 64x32.
// Raw fp32 bits fed to tf32 mma (HW truncates mantissa). Pad-20 smem rows.
// Requires: M % 128 == 0, K % 16 == 0. N guarded via zfill.

#define NSTG 3
#define STG_WORDS 5120          // (128*20) A + (128*20) B per stage
#define SMEM_BYTES (NSTG*STG_WORDS*4)

__device__ __forceinline__ void cp16(unsigned dst, const void* src, bool pred) {
    int sz = pred ? 16 : 0;
    asm volatile("cp.async.cg.shared.global [%0], [%1], 16, %2;\n"
                 :: "r"(dst), "l"(src), "r"(sz));
}
__device__ __forceinline__ void cp_commit() {
    asm volatile("cp.async.commit_group;\n");
}
__device__ __forceinline__ void cp_wait1() {
    asm volatile("cp.async.wait_group 1;\n");
}

__device__ __forceinline__ void mma_tf32(float* d, const unsigned* a, const unsigned* b) {
    asm volatile(
      "mma.sync.aligned.m16n8k8.row.col.f32.tf32.tf32.f32 "
      "{%0,%1,%2,%3}, {%4,%5,%6,%7}, {%8,%9}, {%0,%1,%2,%3};\n"
      : "+f"(d[0]), "+f"(d[1]), "+f"(d[2]), "+f"(d[3])
      : "r"(a[0]), "r"(a[1]), "r"(a[2]), "r"(a[3]), "r"(b[0]), "r"(b[1]));
}

template<int ACT>   // 0 = none, 1 = exact GELU
__global__ void __launch_bounds__(256, 2) gemm_tc(const float* __restrict__ A,
    const float* __restrict__ W, const float* __restrict__ bias,
    const float* __restrict__ res, float* __restrict__ Co,
    int M, int N, int K)
{
    extern __shared__ unsigned sh[];    // NSTG stages: [A 128x20 | B 128x20]

    const int t    = threadIdx.x;
    const int warp = t >> 5;
    const int lane = t & 31;
    const int grp  = lane >> 2;      // 0..7
    const int t4   = lane & 3;       // 0..3
    const int wm   = warp & 1;       // 2 warp-rows of 64
    const int wn   = warp >> 1;      // 4 warp-cols of 32
    const int m0   = blockIdx.y * 128, n0 = blockIdx.x * 128;

    const int lrow = t >> 2;         // 0..63 (load row)
    const int lc4  = (t & 3) * 4;    // 0,4,8,12 (k offset)

    const float* Ag0 = A + (size_t)(m0 + lrow     ) * K + lc4;
    const float* Ag1 = Ag0 + (size_t)64 * K;
    const bool wok0 = (n0 + lrow     ) < N;
    const bool wok1 = (n0 + lrow + 64) < N;
    const float* Wg0 = W + (size_t)(wok0 ? (n0 + lrow     ) : 0) * K + lc4;
    const float* Wg1 = W + (size_t)(wok1 ? (n0 + lrow + 64) : 0) * K + lc4;

    const unsigned sbase = (unsigned)__cvta_generic_to_shared(sh);
    const unsigned dA0 = sbase + ((lrow      )*20 + lc4)*4;
    const unsigned dA1 = sbase + ((lrow + 64 )*20 + lc4)*4;
    const unsigned dB0 = sbase + (2560 + (lrow     )*20 + lc4)*4;
    const unsigned dB1 = sbase + (2560 + (lrow + 64)*20 + lc4)*4;

    float acc[4][4][4];
    #pragma unroll
    for (int i = 0; i < 4; i++)
        #pragma unroll
        for (int j = 0; j < 4; j++)
            #pragma unroll
            for (int r = 0; r < 4; r++) acc[i][j][r] = 0.f;

    const int iters = K >> 4;

    // prologue: stages 0,1
    #pragma unroll
    for (int s = 0; s < NSTG - 1; s++) {
        unsigned off = s * STG_WORDS * 4;
        int ko = s << 4;
        cp16(dA0 + off, Ag0 + ko, true);
        cp16(dA1 + off, Ag1 + ko, true);
        cp16(dB0 + off, Wg0 + ko, wok0);
        cp16(dB1 + off, Wg1 + ko, wok1);
        cp_commit();
    }

    int s = 0;
    for (int it = 0; it < iters; it++) {
        cp_wait1();
        __syncthreads();

        const unsigned* Asm = sh + s * STG_WORDS;
        const unsigned* Bsm = Asm + 2560;

        #pragma unroll
        for (int kb = 0; kb < 16; kb += 8) {
            unsigned af[4][4], bf[4][2];
            #pragma unroll
            for (int mt = 0; mt < 4; mt++) {
                int m = wm*64 + mt*16 + grp;
                af[mt][0] = Asm[(m  )*20 + kb + t4];
                af[mt][1] = Asm[(m+8)*20 + kb + t4];
                af[mt][2] = Asm[(m  )*20 + kb + t4 + 4];
                af[mt][3] = Asm[(m+8)*20 + kb + t4 + 4];
            }
            #pragma unroll
            for (int nt = 0; nt < 4; nt++) {
                int n = wn*32 + nt*8 + grp;
                bf[nt][0] = Bsm[n*20 + kb + t4];
                bf[nt][1] = Bsm[n*20 + kb + t4 + 4];
            }
            #pragma unroll
            for (int mt = 0; mt < 4; mt++)
                #pragma unroll
                for (int nt = 0; nt < 4; nt++)
                    mma_tf32(acc[mt][nt], af[mt], bf[nt]);
        }

        int kt = it + NSTG - 1;
        if (kt < iters) {
            int sn = s + NSTG - 1; if (sn >= NSTG) sn -= NSTG;
            unsigned off = sn * STG_WORDS * 4;
            int ko = kt << 4;
            cp16(dA0 + off, Ag0 + ko, true);
            cp16(dA1 + off, Ag1 + ko, true);
            cp16(dB0 + off, Wg0 + ko, wok0);
            cp16(dB1 + off, Wg1 + ko, wok1);
        }
        cp_commit();
        __syncthreads();
        if (++s == NSTG) s = 0;
    }

    // epilogue
    #pragma unroll
    for (int mt = 0; mt < 4; mt++) {
        #pragma unroll
        for (int nt = 0; nt < 4; nt++) {
            int rbase = m0 + wm*64 + mt*16 + grp;
            int cbase = n0 + wn*32 + nt*8 + t4*2;
            #pragma unroll
            for (int rr = 0; rr < 2; rr++) {
                int m = rbase + rr*8;
                #pragma unroll
                for (int cc = 0; cc < 2; cc++) {
                    int n = cbase + cc;
                    if (n < N) {
                        float v = acc[mt][nt][rr*2 + cc] + bias[n];
                        if (ACT == 1) v = 0.5f*v*(1.f + erff(v*0.70710678118654752f));
                        if (res) v += res[(size_t)m*N + n];
                        Co[(size_t)m*N + n] = v;
                    }
                }
            }
        }
    }
}

// ---------------- Flash self-attention: H=8 heads, D=32, NQ=1024 ---------
#define SD 40   // padded smem row stride
__global__ void __launch_bounds__(256) attn_kernel(const float* __restrict__ qkv,
                                                   float* __restrict__ out)
{
    __shared__ float Qs[64][SD];
    __shared__ float Ks[64][SD];
    __shared__ float Vs[64][SD];
    const int blk = blockIdx.x;
    const int qt = blk & 15;
    const int h  = (blk >> 4) & 7;
    const int b  = blk >> 7;
    const int t  = threadIdx.x;
    const int lane = t & 31;
    const float scale = 0.17677669529663687f;   // 1/sqrt(32)

    const float* qbase = qkv + ((size_t)(b*NQ_ + qt*64))*768 + h*32;
    #pragma unroll
    for (int i = 0; i < 2; i++) {
        int id = t + i*256;                 // float4 id 0..511
        int row = id >> 3, c4 = (id & 7)*4;
        float4 v = *(const float4*)(qbase + (size_t)row*768 + c4);
        v.x *= scale; v.y *= scale; v.z *= scale; v.w *= scale;
        *(float4*)&Qs[row][c4] = v;
    }
    const int r = t >> 2, g = t & 3;
    const float* kbase = qkv + (size_t)(b*NQ_)*768 + 256 + h*32;
    const float* vbase = qkv + (size_t)(b*NQ_)*768 + 512 + h*32;

    float m = -1e30f, l = 0.f;
    float o[8] = {0,0,0,0,0,0,0,0};

    for (int kt = 0; kt < 16; kt++) {
        __syncthreads();
        #pragma unroll
        for (int i = 0; i < 2; i++) {
            int id = t + i*256;
            int row = id >> 3, c4 = (id & 7)*4;
            *(float4*)&Ks[row][c4] = *(const float4*)(kbase + (size_t)(kt*64+row)*768 + c4);
            *(float4*)&Vs[row][c4] = *(const float4*)(vbase + (size_t)(kt*64+row)*768 + c4);
        }
        __syncthreads();

        float s[16];
        #pragma unroll
        for (int kk = 0; kk < 16; kk++) {
            int k2 = kk*4 + g;
            float a = 0.f;
            #pragma unroll
            for (int d4 = 0; d4 < 8; d4++) {
                float4 qv = *(const float4*)&Qs[r][d4*4];
                float4 kv = *(const float4*)&Ks[k2][d4*4];
                a += qv.x*kv.x + qv.y*kv.y + qv.z*kv.z + qv.w*kv.w;
            }
            s[kk] = a;
        }
        float mloc = s[0];
        #pragma unroll
        for (int kk = 1; kk < 16; kk++) mloc = fmaxf(mloc, s[kk]);
        mloc = fmaxf(mloc, __shfl_xor_sync(0xffffffffu, mloc, 1));
        mloc = fmaxf(mloc, __shfl_xor_sync(0xffffffffu, mloc, 2));
        float mnew = fmaxf(m, mloc);
        float corr = __expf(m - mnew);
        float lsum = 0.f;
        #pragma unroll
        for (int kk = 0; kk < 16; kk++) { s[kk] = __expf(s[kk]-mnew); lsum += s[kk]; }
        lsum += __shfl_xor_sync(0xffffffffu, lsum, 1);
        lsum += __shfl_xor_sync(0xffffffffu, lsum, 2);
        l = l*corr + lsum;
        m = mnew;
        #pragma unroll
        for (int j = 0; j < 8; j++) o[j] *= corr;

        const int base_lane = lane & ~3;
        #pragma unroll
        for (int kk = 0; kk < 16; kk++) {
            #pragma unroll
            for (int g2 = 0; g2 < 4; g2++) {
                float p = __shfl_sync(0xffffffffu, s[kk], base_lane + g2);
                int k2 = kk*4 + g2;
                float4 v0 = *(const float4*)&Vs[k2][g*8];
                float4 v1 = *(const float4*)&Vs[k2][g*8+4];
                o[0] += p*v0.x; o[1] += p*v0.y; o[2] += p*v0.z; o[3] += p*v0.w;
                o[4] += p*v1.x; o[5] += p*v1.y; o[6] += p*v1.z; o[7] += p*v1.w;
            }
        }
    }
    float inv = 1.f / l;
    float* ob = out + ((size_t)(b*NQ_ + qt*64 + r))*C_ + h*32 + g*8;
    #pragma unroll
    for (int j = 0; j < 8; j++) ob[j] = o[j]*inv;
}

// ---------------- reference points: sigmoid(q @ ref_w^T + ref_b) ---------
__global__ void __launch_bounds__(256) ref_kernel(const float* __restrict__ q,
    const float* __restrict__ rw, const float* __restrict__ rb,
    float* __restrict__ outp)
{
    int wid = threadIdx.x >> 5, lane = threadIdx.x & 31;
    int row = blockIdx.x*8 + wid;
    const float* x = q + (size_t)row*C_;
    float s0 = 0.f, s1 = 0.f;
    #pragma unroll
    for (int i = 0; i < 8; i++) {
        float xv = x[lane + 32*i];
        s0 += xv * rw[lane + 32*i];
        s1 += xv * rw[C_ + lane + 32*i];
    }
    #pragma unroll
    for (int o = 16; o; o >>= 1) {
        s0 += __shfl_xor_sync(0xffffffffu, s0, o);
        s1 += __shfl_xor_sync(0xffffffffu, s1, o);
    }
    if (lane == 0) {
        outp[(size_t)row*2    ] = 1.f/(1.f + __expf(-(s0 + rb[0])));
        outp[(size_t)row*2 + 1] = 1.f/(1.f + __expf(-(s1 + rb[1])));
    }
}

// ---------------- MSDeformAttn sampling: warp per (b,q,h), lane = channel -
__global__ void __launch_bounds__(256) msdeform_kernel(const float* __restrict__ value,
    const float* __restrict__ ref, const float* __restrict__ so,
    const float* __restrict__ aw, float* __restrict__ outp)
{
    const int wid = threadIdx.x >> 5, lane = threadIdx.x & 31;
    const int gw = blockIdx.x*8 + wid;      // ((b*NQ+q)*8 + h)
    const int h  = gw & 7;
    const int bq = gw >> 3;
    const int b  = bq >> 10;

    // softmax over 24 attention-weight logits (lanes 0..23)
    float logit = -1e30f;
    if (lane < 24) logit = aw[(size_t)bq*192 + h*24 + lane];
    float mx = logit;
    #pragma unroll
    for (int o = 16; o; o >>= 1) mx = fmaxf(mx, __shfl_xor_sync(0xffffffffu, mx, o));
    float e = (lane < 24) ? __expf(logit - mx) : 0.f;
    float ssum = e;
    #pragma unroll
    for (int o = 16; o; o >>= 1) ssum += __shfl_xor_sync(0xffffffffu, ssum, o);
    float pw = e / ssum;

    // sampling offsets (lanes 0..23 hold their own point)
    float offx = 0.f, offy = 0.f;
    if (lane < 24) {
        int l = lane >> 3, p = lane & 7;
        const float* sp = so + (size_t)bq*384 + ((size_t)((h*3 + l)*8 + p))*2;
        offx = sp[0]; offy = sp[1];
    }
    float rx = ref[(size_t)bq*2], ry = ref[(size_t)bq*2 + 1];

    const int HL[3] = {128, 64, 32};
    const int WL[3] = {128, 64, 32};
    const int ST[3] = {0, 16384, 20480};

    float acc = 0.f;
    #pragma unroll
    for (int l = 0; l < 3; l++) {
        const int h_l = HL[l], w_l = WL[l], start = ST[l];
        const float gxb = rx * (float)w_l - 0.5f;
        const float gyb = ry * (float)h_l - 0.5f;
        const float* vb = value + ((size_t)(b*S_ + start))*C_ + h*32 + lane;
        #pragma unroll
        for (int p = 0; p < 8; p++) {
            int lp = l*8 + p;
            float ox = __shfl_sync(0xffffffffu, offx, lp);
            float oy = __shfl_sync(0xffffffffu, offy, lp);
            float w  = __shfl_sync(0xffffffffu, pw,   lp);
            float gx = gxb + ox;
            float gy = gyb + oy;
            float x0f = floorf(gx), y0f = floorf(gy);
            float lx = gx - x0f, ly = gy - y0f;
            int x0 = (int)x0f, y0 = (int)y0f;
            float w00 = (1.f-lx)*(1.f-ly)*w;
            float w01 = lx*(1.f-ly)*w;
            float w10 = (1.f-lx)*ly*w;
            float w11 = lx*ly*w;
            bool vx0 = (x0   >= 0) & (x0   < w_l);
            bool vx1 = (x0+1 >= 0) & (x0+1 < w_l);
            if (y0 >= 0 && y0 < h_l) {
                const float* rowp = vb + (size_t)y0*w_l*C_;
                if (vx0) acc += w00 * rowp[(size_t)x0*C_];
                if (vx1) acc += w01 * rowp[(size_t)(x0+1)*C_];
            }
            if (y0+1 >= 0 && y0+1 < h_l) {
                const float* rowp = vb + (size_t)(y0+1)*w_l*C_;
                if (vx0) acc += w10 * rowp[(size_t)x0*C_];
                if (vx1) acc += w11 * rowp[(size_t)(x0+1)*C_];
            }
        }
    }
    outp[(size_t)bq*C_ + h*32 + lane] = acc;
}

// ---------------- launch ----------------
extern "C" void kernel_launch(void* const* d_in, const int* in_sizes, int n_in,
                              void* d_out, int out_size)
{
    const float* tgt    = (const float*)d_in[0];
    const float* memory = (const float*)d_in[1];
    const float* n1w = (const float*)d_in[2];
    const float* n1b = (const float*)d_in[3];
    const float* inw = (const float*)d_in[4];
    const float* inb = (const float*)d_in[5];
    const float* outw= (const float*)d_in[6];
    const float* outb= (const float*)d_in[7];
    const float* n2w = (const float*)d_in[8];
    const float* n2b = (const float*)d_in[9];
    const float* refw= (const float*)d_in[10];
    const float* refb= (const float*)d_in[11];
    const float* sow = (const float*)d_in[12];
    const float* sob = (const float*)d_in[13];
    const float* aww = (const float*)d_in[14];
    const float* awb = (const float*)d_in[15];
    const float* vpw = (const float*)d_in[16];
    const float* vpb = (const float*)d_in[17];
    const float* opw = (const float*)d_in[18];
    const float* opb = (const float*)d_in[19];
    const float* n3w = (const float*)d_in[20];
    const float* n3b = (const float*)d_in[21];
    const float* l1w = (const float*)d_in[22];
    const float* l1b = (const float*)d_in[23];
    const float* l2w = (const float*)d_in[24];
    const float* l2b = (const float*)d_in[25];

    float *q, *qkv, *attn, *tgt2, *tgt3, *val, *so, *aw, *refo, *ca, *ff1;
    cudaGetSymbolAddress((void**)&q,    g_q);
    cudaGetSymbolAddress((void**)&qkv,  g_qkv);
    cudaGetSymbolAddress((void**)&attn, g_attn);
    cudaGetSymbolAddress((void**)&tgt2, g_tgt2);
    cudaGetSymbolAddress((void**)&tgt3, g_tgt3);
    cudaGetSymbolAddress((void**)&val,  g_val);
    cudaGetSymbolAddress((void**)&so,   g_so);
    cudaGetSymbolAddress((void**)&aw,   g_aw);
    cudaGetSymbolAddress((void**)&refo, g_ref);
    cudaGetSymbolAddress((void**)&ca,   g_ca);
    cudaGetSymbolAddress((void**)&ff1,  g_ff1);

    cudaFuncSetAttribute(gemm_tc<0>, cudaFuncAttributeMaxDynamicSharedMemorySize, SMEM_BYTES);
    cudaFuncSetAttribute(gemm_tc<1>, cudaFuncAttributeMaxDynamicSharedMemorySize, SMEM_BYTES);

    // 1. q1 = LN(tgt)
    ln_kernel<<<BNQ, 256>>>(tgt, n1w, n1b, q);
    // 2. qkv = q1 @ in_w^T + in_b
    gemm_tc<0><<<dim3(768/128, BNQ/128), 256, SMEM_BYTES>>>(q, inw, inb, nullptr, qkv, BNQ, 768, C_);
    // 3. self-attention
    attn_kernel<<<B_*8*16, 256>>>(qkv, attn);
    // 4. tgt2 = tgt + attn @ out_w^T + out_b
    gemm_tc<0><<<dim3(C_/128, BNQ/128), 256, SMEM_BYTES>>>(attn, outw, outb, tgt, tgt2, BNQ, C_, C_);
    // 5. q2 = LN(tgt2)
    ln_kernel<<<BNQ, 256>>>(tgt2, n2w, n2b, q);
    // 6. value = memory @ vp_w^T + vp_b (the big one)
    gemm_tc<0><<<dim3(C_/128, BS_/128), 256, SMEM_BYTES>>>(memory, vpw, vpb, nullptr, val, BS_, C_, C_);
    // 7. sampling offsets
    gemm_tc<0><<<dim3(3, BNQ/128), 256, SMEM_BYTES>>>(q, sow, sob, nullptr, so, BNQ, 384, C_);
    // 8. attention weight logits (N=192, guarded)
    gemm_tc<0><<<dim3(2, BNQ/128), 256, SMEM_BYTES>>>(q, aww, awb, nullptr, aw, BNQ, 192, C_);
    // 9. reference points
    ref_kernel<<<BNQ/8, 256>>>(q, refw, refb, refo);
    // 10. deformable sampling
    msdeform_kernel<<<BNQ, 256>>>(val, refo, so, aw, ca);
    // 11. tgt3 = tgt2 + ca @ op_w^T + op_b
    gemm_tc<0><<<dim3(C_/128, BNQ/128), 256, SMEM_BYTES>>>(ca, opw, opb, tgt2, tgt3, BNQ, C_, C_);
    // 12. q3 = LN(tgt3)
    ln_kernel<<<BNQ, 256>>>(tgt3, n3w, n3b, q);
    // 13. ff1 = gelu(q3 @ l1_w^T + l1_b)
    gemm_tc<1><<<dim3(1024/128, BNQ/128), 256, SMEM_BYTES>>>(q, l1w, l1b, nullptr, ff1, BNQ, 1024, C_);
    // 14. out = tgt3 + ff1 @ l2_w^T + l2_b
    gemm_tc<0><<<dim3(C_/128, BNQ/128), 256, SMEM_BYTES>>>(ff1, l2w, l2b, tgt3, (float*)d_out, BNQ, C_, 1024);
}

// round 4
// speedup vs baseline: 3.0107x; 1.6754x over previous
#include <cuda_runtime.h>
#include <math.h>

// Problem constants
#define B_   8
#define NQ_  1024
#define C_   256
#define S_   21504
#define BNQ  (B_*NQ_)      // 8192 rows
#define BS_  (B_*S_)       // 172032 rows

// ---------------- device scratch (no allocations allowed) ----------------
__device__ float g_q   [BNQ*C_];        // shared LN output buffer (q1/q2/q3)
__device__ float g_qkv [BNQ*3*C_];
__device__ float g_attn[BNQ*C_];
__device__ float g_tgt2[BNQ*C_];
__device__ float g_tgt3[BNQ*C_];
__device__ float g_val [BS_*(size_t)C_];
__device__ float g_so  [BNQ*384];
__device__ float g_aw  [BNQ*192];
__device__ float g_ref [BNQ*2];
__device__ float g_ca  [BNQ*C_];
__device__ float g_ff1 [BNQ*1024];

// ---------------- LayerNorm: one block (256 thr) per row, C=256 ----------
__global__ void __launch_bounds__(256) ln_kernel(const float* __restrict__ x,
    const float* __restrict__ w, const float* __restrict__ b,
    float* __restrict__ y)
{
    int row = blockIdx.x;
    float v = x[(size_t)row*C_ + threadIdx.x];
    float s = v, s2 = v*v;
    __shared__ float red[16];
    int lane = threadIdx.x & 31, wid = threadIdx.x >> 5;
    #pragma unroll
    for (int o = 16; o; o >>= 1) {
        s  += __shfl_xor_sync(0xffffffffu, s,  o);
        s2 += __shfl_xor_sync(0xffffffffu, s2, o);
    }
    if (lane == 0) { red[wid] = s; red[wid+8] = s2; }
    __syncthreads();
    float ts = 0.f, ts2 = 0.f;
    #pragma unroll
    for (int i = 0; i < 8; i++) { ts += red[i]; ts2 += red[i+8]; }
    float mean = ts * (1.f/C_);
    float var  = ts2 * (1.f/C_) - mean*mean;
    float r = rsqrtf(var + 1e-5f);
    y[(size_t)row*C_ + threadIdx.x] = (v - mean)*r*w[threadIdx.x] + b[threadIdx.x];
}

// ---------------- TF32 tensor-core GEMM (cp.async 3-stage) ---------------
#define NSTG 3
#define STG_WORDS 5120          // (128*20) A + (128*20) B per stage
#define SMEM_BYTES (NSTG*STG_WORDS*4)

__device__ __forceinline__ void cp16(unsigned dst, const void* src, bool pred) {
    int sz = pred ? 16 : 0;
    asm volatile("cp.async.cg.shared.global [%0], [%1], 16, %2;\n"
                 :: "r"(dst), "l"(src), "r"(sz));
}
__device__ __forceinline__ void cp_commit() {
    asm volatile("cp.async.commit_group;\n");
}
__device__ __forceinline__ void cp_wait1() {
    asm volatile("cp.async.wait_group 1;\n");
}

__device__ __forceinline__ void mma_tf32(float* d, const unsigned* a, const unsigned* b) {
    asm volatile(
      "mma.sync.aligned.m16n8k8.row.col.f32.tf32.tf32.f32 "
      "{%0,%1,%2,%3}, {%4,%5,%6,%7}, {%8,%9}, {%0,%1,%2,%3};\n"
      : "+f"(d[0]), "+f"(d[1]), "+f"(d[2]), "+f"(d[3])
      : "r"(a[0]), "r"(a[1]), "r"(a[2]), "r"(a[3]), "r"(b[0]), "r"(b[1]));
}

template<int ACT>   // 0 = none, 1 = exact GELU
__global__ void __launch_bounds__(256, 2) gemm_tc(const float* __restrict__ A,
    const float* __restrict__ W, const float* __restrict__ bias,
    const float* __restrict__ res, float* __restrict__ Co,
    int M, int N, int K)
{
    extern __shared__ unsigned sh[];    // NSTG stages: [A 128x20 | B 128x20]

    const int t    = threadIdx.x;
    const int warp = t >> 5;
    const int lane = t & 31;
    const int grp  = lane >> 2;      // 0..7
    const int t4   = lane & 3;       // 0..3
    const int wm   = warp & 1;       // 2 warp-rows of 64
    const int wn   = warp >> 1;      // 4 warp-cols of 32
    const int m0   = blockIdx.y * 128, n0 = blockIdx.x * 128;

    const int lrow = t >> 2;         // 0..63 (load row)
    const int lc4  = (t & 3) * 4;    // 0,4,8,12 (k offset)

    const float* Ag0 = A + (size_t)(m0 + lrow     ) * K + lc4;
    const float* Ag1 = Ag0 + (size_t)64 * K;
    const bool wok0 = (n0 + lrow     ) < N;
    const bool wok1 = (n0 + lrow + 64) < N;
    const float* Wg0 = W + (size_t)(wok0 ? (n0 + lrow     ) : 0) * K + lc4;
    const float* Wg1 = W + (size_t)(wok1 ? (n0 + lrow + 64) : 0) * K + lc4;

    const unsigned sbase = (unsigned)__cvta_generic_to_shared(sh);
    const unsigned dA0 = sbase + ((lrow      )*20 + lc4)*4;
    const unsigned dA1 = sbase + ((lrow + 64 )*20 + lc4)*4;
    const unsigned dB0 = sbase + (2560 + (lrow     )*20 + lc4)*4;
    const unsigned dB1 = sbase + (2560 + (lrow + 64)*20 + lc4)*4;

    float acc[4][4][4];
    #pragma unroll
    for (int i = 0; i < 4; i++)
        #pragma unroll
        for (int j = 0; j < 4; j++)
            #pragma unroll
            for (int r = 0; r < 4; r++) acc[i][j][r] = 0.f;

    const int iters = K >> 4;

    // prologue: stages 0,1
    #pragma unroll
    for (int s = 0; s < NSTG - 1; s++) {
        unsigned off = s * STG_WORDS * 4;
        int ko = s << 4;
        cp16(dA0 + off, Ag0 + ko, true);
        cp16(dA1 + off, Ag1 + ko, true);
        cp16(dB0 + off, Wg0 + ko, wok0);
        cp16(dB1 + off, Wg1 + ko, wok1);
        cp_commit();
    }

    int s = 0;
    for (int it = 0; it < iters; it++) {
        cp_wait1();
        __syncthreads();

        const unsigned* Asm = sh + s * STG_WORDS;
        const unsigned* Bsm = Asm + 2560;

        #pragma unroll
        for (int kb = 0; kb < 16; kb += 8) {
            unsigned af[4][4], bf[4][2];
            #pragma unroll
            for (int mt = 0; mt < 4; mt++) {
                int m = wm*64 + mt*16 + grp;
                af[mt][0] = Asm[(m  )*20 + kb + t4];
                af[mt][1] = Asm[(m+8)*20 + kb + t4];
                af[mt][2] = Asm[(m  )*20 + kb + t4 + 4];
                af[mt][3] = Asm[(m+8)*20 + kb + t4 + 4];
            }
            #pragma unroll
            for (int nt = 0; nt < 4; nt++) {
                int n = wn*32 + nt*8 + grp;
                bf[nt][0] = Bsm[n*20 + kb + t4];
                bf[nt][1] = Bsm[n*20 + kb + t4 + 4];
            }
            #pragma unroll
            for (int mt = 0; mt < 4; mt++)
                #pragma unroll
                for (int nt = 0; nt < 4; nt++)
                    mma_tf32(acc[mt][nt], af[mt], bf[nt]);
        }

        int kt = it + NSTG - 1;
        if (kt < iters) {
            int sn = s + NSTG - 1; if (sn >= NSTG) sn -= NSTG;
            unsigned off = sn * STG_WORDS * 4;
            int ko = kt << 4;
            cp16(dA0 + off, Ag0 + ko, true);
            cp16(dA1 + off, Ag1 + ko, true);
            cp16(dB0 + off, Wg0 + ko, wok0);
            cp16(dB1 + off, Wg1 + ko, wok1);
        }
        cp_commit();
        __syncthreads();
        if (++s == NSTG) s = 0;
    }

    // epilogue
    #pragma unroll
    for (int mt = 0; mt < 4; mt++) {
        #pragma unroll
        for (int nt = 0; nt < 4; nt++) {
            int rbase = m0 + wm*64 + mt*16 + grp;
            int cbase = n0 + wn*32 + nt*8 + t4*2;
            #pragma unroll
            for (int rr = 0; rr < 2; rr++) {
                int m = rbase + rr*8;
                #pragma unroll
                for (int cc = 0; cc < 2; cc++) {
                    int n = cbase + cc;
                    if (n < N) {
                        float v = acc[mt][nt][rr*2 + cc] + bias[n];
                        if (ACT == 1) v = 0.5f*v*(1.f + erff(v*0.70710678118654752f));
                        if (res) v += res[(size_t)m*N + n];
                        Co[(size_t)m*N + n] = v;
                    }
                }
            }
        }
    }
}

// ---------------- Flash self-attention (TF32 MMA) -------------------------
// CTA = (b, h, 128-query tile). 8 warps, warp owns 16 query rows.
// QK^T and PV both on m16n8k8 tf32. K smem stride 36, V^T smem stride 68
// (both conflict-free for the fragment access patterns).
__global__ void __launch_bounds__(256) attn_mma(const float* __restrict__ qkv,
                                                float* __restrict__ out)
{
    __shared__ float Ks[64][36];
    __shared__ float Vt[32][68];

    const int bx = blockIdx.x;
    const int qt = bx & 7;            // 8 q-tiles of 128
    const int h  = (bx >> 3) & 7;
    const int b  = bx >> 6;
    const int t = threadIdx.x, warp = t >> 5, lane = t & 31;
    const int grp = lane >> 2, t4 = lane & 3;
    const int q0 = qt*128, wq = warp*16;

    const float scale = 0.17677669529663687f;  // 1/sqrt(32)

    // Q fragments (m16 x k32), scale folded in
    const float* qb = qkv + ((size_t)(b*NQ_ + q0 + wq))*768 + h*32;
    unsigned Qf[4][4];
    #pragma unroll
    for (int kb = 0; kb < 4; kb++) {
        Qf[kb][0] = __float_as_uint(qb[(size_t)(grp  )*768 + kb*8 + t4    ] * scale);
        Qf[kb][1] = __float_as_uint(qb[(size_t)(grp+8)*768 + kb*8 + t4    ] * scale);
        Qf[kb][2] = __float_as_uint(qb[(size_t)(grp  )*768 + kb*8 + t4 + 4] * scale);
        Qf[kb][3] = __float_as_uint(qb[(size_t)(grp+8)*768 + kb*8 + t4 + 4] * scale);
    }

    float m_a = -1e30f, m_b = -1e30f, l_a = 0.f, l_b = 0.f;
    float oac[4][4];
    #pragma unroll
    for (int i = 0; i < 4; i++)
        #pragma unroll
        for (int j = 0; j < 4; j++) oac[i][j] = 0.f;

    const float* kg = qkv + (size_t)(b*NQ_)*768 + 256 + h*32;
    const float* vg = qkv + (size_t)(b*NQ_)*768 + 512 + h*32;

    const int lrow = t >> 2;          // 0..63
    const int lc4  = (t & 3) * 4;     // 0,4,8,12

    for (int kt = 0; kt < 16; kt++) {
        __syncthreads();
        {   // load K tile [64][32] and V tile transposed [32][64]
            const float* src = kg + (size_t)(kt*64 + lrow)*768;
            float4 v0 = *(const float4*)(src + lc4);
            float4 v1 = *(const float4*)(src + lc4 + 16);
            *(float4*)&Ks[lrow][lc4]      = v0;
            *(float4*)&Ks[lrow][lc4 + 16] = v1;
            const float* sv = vg + (size_t)(kt*64 + lrow)*768;
            float4 w0 = *(const float4*)(sv + lc4);
            float4 w1 = *(const float4*)(sv + lc4 + 16);
            Vt[lc4+0 ][lrow] = w0.x; Vt[lc4+1 ][lrow] = w0.y;
            Vt[lc4+2 ][lrow] = w0.z; Vt[lc4+3 ][lrow] = w0.w;
            Vt[lc4+16][lrow] = w1.x; Vt[lc4+17][lrow] = w1.y;
            Vt[lc4+18][lrow] = w1.z; Vt[lc4+19][lrow] = w1.w;
        }
        __syncthreads();

        // S = Q @ K^T : m16 x n64
        float sacc[8][4];
        #pragma unroll
        for (int nt = 0; nt < 8; nt++)
            #pragma unroll
            for (int r = 0; r < 4; r++) sacc[nt][r] = 0.f;
        #pragma unroll
        for (int kb = 0; kb < 4; kb++) {
            #pragma unroll
            for (int nt = 0; nt < 8; nt++) {
                unsigned bf[2];
                bf[0] = __float_as_uint(Ks[nt*8 + grp][kb*8 + t4    ]);
                bf[1] = __float_as_uint(Ks[nt*8 + grp][kb*8 + t4 + 4]);
                mma_tf32(sacc[nt], Qf[kb], bf);
            }
        }

        // online softmax (rows grp and grp+8)
        float mx_a = -1e30f, mx_b = -1e30f;
        #pragma unroll
        for (int nt = 0; nt < 8; nt++) {
            mx_a = fmaxf(mx_a, fmaxf(sacc[nt][0], sacc[nt][1]));
            mx_b = fmaxf(mx_b, fmaxf(sacc[nt][2], sacc[nt][3]));
        }
        mx_a = fmaxf(mx_a, __shfl_xor_sync(0xffffffffu, mx_a, 1));
        mx_a = fmaxf(mx_a, __shfl_xor_sync(0xffffffffu, mx_a, 2));
        mx_b = fmaxf(mx_b, __shfl_xor_sync(0xffffffffu, mx_b, 1));
        mx_b = fmaxf(mx_b, __shfl_xor_sync(0xffffffffu, mx_b, 2));
        float mna = fmaxf(m_a, mx_a), mnb = fmaxf(m_b, mx_b);
        float ca = __expf(m_a - mna), cb = __expf(m_b - mnb);
        float sa = 0.f, sb = 0.f;
        #pragma unroll
        for (int nt = 0; nt < 8; nt++) {
            sacc[nt][0] = __expf(sacc[nt][0] - mna);
            sacc[nt][1] = __expf(sacc[nt][1] - mna);
            sacc[nt][2] = __expf(sacc[nt][2] - mnb);
            sacc[nt][3] = __expf(sacc[nt][3] - mnb);
            sa += sacc[nt][0] + sacc[nt][1];
            sb += sacc[nt][2] + sacc[nt][3];
        }
        sa += __shfl_xor_sync(0xffffffffu, sa, 1);
        sa += __shfl_xor_sync(0xffffffffu, sa, 2);
        sb += __shfl_xor_sync(0xffffffffu, sb, 1);
        sb += __shfl_xor_sync(0xffffffffu, sb, 2);
        l_a = l_a*ca + sa;  l_b = l_b*cb + sb;
        m_a = mna;          m_b = mnb;
        #pragma unroll
        for (int nt = 0; nt < 4; nt++) {
            oac[nt][0] *= ca; oac[nt][1] *= ca;
            oac[nt][2] *= cb; oac[nt][3] *= cb;
        }

        // O += P @ V  (P accumulator-layout -> A-fragment via shfl)
        const int srcA = (lane & ~3) + (t4 >> 1);
        const int srcB = srcA + 2;
        const bool odd = (t4 & 1);
        #pragma unroll
        for (int j = 0; j < 8; j++) {
            float p00 = __shfl_sync(0xffffffffu, sacc[j][0], srcA);
            float p01 = __shfl_sync(0xffffffffu, sacc[j][1], srcA);
            float p04 = __shfl_sync(0xffffffffu, sacc[j][0], srcB);
            float p05 = __shfl_sync(0xffffffffu, sacc[j][1], srcB);
            float p10 = __shfl_sync(0xffffffffu, sacc[j][2], srcA);
            float p11 = __shfl_sync(0xffffffffu, sacc[j][3], srcA);
            float p14 = __shfl_sync(0xffffffffu, sacc[j][2], srcB);
            float p15 = __shfl_sync(0xffffffffu, sacc[j][3], srcB);
            unsigned pa[4];
            pa[0] = __float_as_uint(odd ? p01 : p00);
            pa[1] = __float_as_uint(odd ? p11 : p10);
            pa[2] = __float_as_uint(odd ? p05 : p04);
            pa[3] = __float_as_uint(odd ? p15 : p14);
            #pragma unroll
            for (int nt = 0; nt < 4; nt++) {
                unsigned bf[2];
                bf[0] = __float_as_uint(Vt[nt*8 + grp][j*8 + t4    ]);
                bf[1] = __float_as_uint(Vt[nt*8 + grp][j*8 + t4 + 4]);
                mma_tf32(oac[nt], pa, bf);
            }
        }
    }

    float inva = 1.f / l_a, invb = 1.f / l_b;
    float* ob = out + ((size_t)(b*NQ_ + q0 + wq))*C_ + h*32;
    #pragma unroll
    for (int nt = 0; nt < 4; nt++) {
        ob[(size_t)(grp  )*C_ + nt*8 + 2*t4    ] = oac[nt][0]*inva;
        ob[(size_t)(grp  )*C_ + nt*8 + 2*t4 + 1] = oac[nt][1]*inva;
        ob[(size_t)(grp+8)*C_ + nt*8 + 2*t4    ] = oac[nt][2]*invb;
        ob[(size_t)(grp+8)*C_ + nt*8 + 2*t4 + 1] = oac[nt][3]*invb;
    }
}

// ---------------- reference points: sigmoid(q @ ref_w^T + ref_b) ---------
__global__ void __launch_bounds__(256) ref_kernel(const float* __restrict__ q,
    const float* __restrict__ rw, const float* __restrict__ rb,
    float* __restrict__ outp)
{
    int wid = threadIdx.x >> 5, lane = threadIdx.x & 31;
    int row = blockIdx.x*8 + wid;
    const float* x = q + (size_t)row*C_;
    float s0 = 0.f, s1 = 0.f;
    #pragma unroll
    for (int i = 0; i < 8; i++) {
        float xv = x[lane + 32*i];
        s0 += xv * rw[lane + 32*i];
        s1 += xv * rw[C_ + lane + 32*i];
    }
    #pragma unroll
    for (int o = 16; o; o >>= 1) {
        s0 += __shfl_xor_sync(0xffffffffu, s0, o);
        s1 += __shfl_xor_sync(0xffffffffu, s1, o);
    }
    if (lane == 0) {
        outp[(size_t)row*2    ] = 1.f/(1.f + __expf(-(s0 + rb[0])));
        outp[(size_t)row*2 + 1] = 1.f/(1.f + __expf(-(s1 + rb[1])));
    }
}

// ---------------- MSDeformAttn sampling: warp per (b,q,h), lane = channel -
__global__ void __launch_bounds__(256) msdeform_kernel(const float* __restrict__ value,
    const float* __restrict__ ref, const float* __restrict__ so,
    const float* __restrict__ aw, float* __restrict__ outp)
{
    const int wid = threadIdx.x >> 5, lane = threadIdx.x & 31;
    const int gw = blockIdx.x*8 + wid;      // ((b*NQ+q)*8 + h)
    const int h  = gw & 7;
    const int bq = gw >> 3;
    const int b  = bq >> 10;

    // softmax over 24 attention-weight logits (lanes 0..23)
    float logit = -1e30f;
    if (lane < 24) logit = aw[(size_t)bq*192 + h*24 + lane];
    float mx = logit;
    #pragma unroll
    for (int o = 16; o; o >>= 1) mx = fmaxf(mx, __shfl_xor_sync(0xffffffffu, mx, o));
    float e = (lane < 24) ? __expf(logit - mx) : 0.f;
    float ssum = e;
    #pragma unroll
    for (int o = 16; o; o >>= 1) ssum += __shfl_xor_sync(0xffffffffu, ssum, o);
    float pw = e / ssum;

    // sampling offsets (lanes 0..23 hold their own point)
    float offx = 0.f, offy = 0.f;
    if (lane < 24) {
        int l = lane >> 3, p = lane & 7;
        const float* sp = so + (size_t)bq*384 + ((size_t)((h*3 + l)*8 + p))*2;
        offx = sp[0]; offy = sp[1];
    }
    float rx = ref[(size_t)bq*2], ry = ref[(size_t)bq*2 + 1];

    const int HL[3] = {128, 64, 32};
    const int WL[3] = {128, 64, 32};
    const int ST[3] = {0, 16384, 20480};

    float acc = 0.f;
    #pragma unroll
    for (int l = 0; l < 3; l++) {
        const int h_l = HL[l], w_l = WL[l], start = ST[l];
        const float gxb = rx * (float)w_l - 0.5f;
        const float gyb = ry * (float)h_l - 0.5f;
        const float* vb = value + ((size_t)(b*S_ + start))*C_ + h*32 + lane;
        #pragma unroll
        for (int p = 0; p < 8; p++) {
            int lp = l*8 + p;
            float ox = __shfl_sync(0xffffffffu, offx, lp);
            float oy = __shfl_sync(0xffffffffu, offy, lp);
            float w  = __shfl_sync(0xffffffffu, pw,   lp);
            float gx = gxb + ox;
            float gy = gyb + oy;
            float x0f = floorf(gx), y0f = floorf(gy);
            float lx = gx - x0f, ly = gy - y0f;
            int x0 = (int)x0f, y0 = (int)y0f;
            float w00 = (1.f-lx)*(1.f-ly)*w;
            float w01 = lx*(1.f-ly)*w;
            float w10 = (1.f-lx)*ly*w;
            float w11 = lx*ly*w;
            bool vx0 = (x0   >= 0) & (x0   < w_l);
            bool vx1 = (x0+1 >= 0) & (x0+1 < w_l);
            if (y0 >= 0 && y0 < h_l) {
                const float* rowp = vb + (size_t)y0*w_l*C_;
                if (vx0) acc += w00 * rowp[(size_t)x0*C_];
                if (vx1) acc += w01 * rowp[(size_t)(x0+1)*C_];
            }
            if (y0+1 >= 0 && y0+1 < h_l) {
                const float* rowp = vb + (size_t)(y0+1)*w_l*C_;
                if (vx0) acc += w10 * rowp[(size_t)x0*C_];
                if (vx1) acc += w11 * rowp[(size_t)(x0+1)*C_];
            }
        }
    }
    outp[(size_t)bq*C_ + h*32 + lane] = acc;
}

// ---------------- launch ----------------
extern "C" void kernel_launch(void* const* d_in, const int* in_sizes, int n_in,
                              void* d_out, int out_size)
{
    const float* tgt    = (const float*)d_in[0];
    const float* memory = (const float*)d_in[1];
    const float* n1w = (const float*)d_in[2];
    const float* n1b = (const float*)d_in[3];
    const float* inw = (const float*)d_in[4];
    const float* inb = (const float*)d_in[5];
    const float* outw= (const float*)d_in[6];
    const float* outb= (const float*)d_in[7];
    const float* n2w = (const float*)d_in[8];
    const float* n2b = (const float*)d_in[9];
    const float* refw= (const float*)d_in[10];
    const float* refb= (const float*)d_in[11];
    const float* sow = (const float*)d_in[12];
    const float* sob = (const float*)d_in[13];
    const float* aww = (const float*)d_in[14];
    const float* awb = (const float*)d_in[15];
    const float* vpw = (const float*)d_in[16];
    const float* vpb = (const float*)d_in[17];
    const float* opw = (const float*)d_in[18];
    const float* opb = (const float*)d_in[19];
    const float* n3w = (const float*)d_in[20];
    const float* n3b = (const float*)d_in[21];
    const float* l1w = (const float*)d_in[22];
    const float* l1b = (const float*)d_in[23];
    const float* l2w = (const float*)d_in[24];
    const float* l2b = (const float*)d_in[25];

    float *q, *qkv, *attn, *tgt2, *tgt3, *val, *so, *aw, *refo, *ca, *ff1;
    cudaGetSymbolAddress((void**)&q,    g_q);
    cudaGetSymbolAddress((void**)&qkv,  g_qkv);
    cudaGetSymbolAddress((void**)&attn, g_attn);
    cudaGetSymbolAddress((void**)&tgt2, g_tgt2);
    cudaGetSymbolAddress((void**)&tgt3, g_tgt3);
    cudaGetSymbolAddress((void**)&val,  g_val);
    cudaGetSymbolAddress((void**)&so,   g_so);
    cudaGetSymbolAddress((void**)&aw,   g_aw);
    cudaGetSymbolAddress((void**)&refo, g_ref);
    cudaGetSymbolAddress((void**)&ca,   g_ca);
    cudaGetSymbolAddress((void**)&ff1,  g_ff1);

    // one-time resources (host-side only; no device memory involved)
    static cudaStream_t s2 = 0;
    static cudaEvent_t evFork = 0, evJoin = 0;
    if (!s2) {
        cudaStreamCreateWithFlags(&s2, cudaStreamNonBlocking);
        cudaEventCreateWithFlags(&evFork, cudaEventDisableTiming);
        cudaEventCreateWithFlags(&evJoin, cudaEventDisableTiming);
        cudaFuncSetAttribute(gemm_tc<0>, cudaFuncAttributeMaxDynamicSharedMemorySize, SMEM_BYTES);
        cudaFuncSetAttribute(gemm_tc<1>, cudaFuncAttributeMaxDynamicSharedMemorySize, SMEM_BYTES);
    }

    // ---- fork: value projection runs concurrently on s2 ----
    cudaEventRecord(evFork, 0);
    cudaStreamWaitEvent(s2, evFork, 0);
    gemm_tc<0><<<dim3(C_/128, BS_/128), 256, SMEM_BYTES, s2>>>(memory, vpw, vpb, nullptr, val, BS_, C_, C_);
    cudaEventRecord(evJoin, s2);

    // ---- main chain (stream 0) ----
    // 1. q1 = LN(tgt)
    ln_kernel<<<BNQ, 256>>>(tgt, n1w, n1b, q);
    // 2. qkv = q1 @ in_w^T + in_b
    gemm_tc<0><<<dim3(768/128, BNQ/128), 256, SMEM_BYTES>>>(q, inw, inb, nullptr, qkv, BNQ, 768, C_);
    // 3. self-attention (tensor cores)
    attn_mma<<<B_*8*8, 256>>>(qkv, attn);
    // 4. tgt2 = tgt + attn @ out_w^T + out_b
    gemm_tc<0><<<dim3(C_/128, BNQ/128), 256, SMEM_BYTES>>>(attn, outw, outb, tgt, tgt2, BNQ, C_, C_);
    // 5. q2 = LN(tgt2)
    ln_kernel<<<BNQ, 256>>>(tgt2, n2w, n2b, q);
    // 6. sampling offsets
    gemm_tc<0><<<dim3(3, BNQ/128), 256, SMEM_BYTES>>>(q, sow, sob, nullptr, so, BNQ, 384, C_);
    // 7. attention weight logits (N=192, guarded)
    gemm_tc<0><<<dim3(2, BNQ/128), 256, SMEM_BYTES>>>(q, aww, awb, nullptr, aw, BNQ, 192, C_);
    // 8. reference points
    ref_kernel<<<BNQ/8, 256>>>(q, refw, refb, refo);

    // ---- join: need value ready before sampling ----
    cudaStreamWaitEvent(0, evJoin, 0);

    // 9. deformable sampling
    msdeform_kernel<<<BNQ, 256>>>(val, refo, so, aw, ca);
    // 10. tgt3 = tgt2 + ca @ op_w^T + op_b
    gemm_tc<0><<<dim3(C_/128, BNQ/128), 256, SMEM_BYTES>>>(ca, opw, opb, tgt2, tgt3, BNQ, C_, C_);
    // 11. q3 = LN(tgt3)
    ln_kernel<<<BNQ, 256>>>(tgt3, n3w, n3b, q);
    // 12. ff1 = gelu(q3 @ l1_w^T + l1_b)
    gemm_tc<1><<<dim3(1024/128, BNQ/128), 256, SMEM_BYTES>>>(q, l1w, l1b, nullptr, ff1, BNQ, 1024, C_);
    // 13. out = tgt3 + ff1 @ l2_w^T + l2_b
    gemm_tc<0><<<dim3(C_/128, BNQ/128), 256, SMEM_BYTES>>>(ff1, l2w, l2b, tgt3, (float*)d_out, BNQ, C_, 1024);
}

// round 5
// speedup vs baseline: 3.2083x; 1.0656x over previous
#include <cuda_runtime.h>
#include <cuda_bf16.h>
#include <math.h>

// Problem constants
#define B_   8
#define NQ_  1024
#define C_   256
#define S_   21504
#define BNQ  (B_*NQ_)      // 8192 rows
#define BS_  (B_*S_)       // 172032 rows

// ---------------- device scratch (no allocations allowed) ----------------
__device__ float g_q   [BNQ*C_];        // shared LN output buffer (q1/q2/q3)
__device__ float g_qkv [BNQ*3*C_];
__device__ float g_attn[BNQ*C_];
__device__ float g_tgt2[BNQ*C_];
__device__ float g_tgt3[BNQ*C_];
__device__ float g_val [BS_*(size_t)C_];
__device__ float g_so  [BNQ*384];
__device__ float g_aw  [BNQ*192];
__device__ float g_ref [BNQ*2];
__device__ float g_ca  [BNQ*C_];
__device__ float g_ff1 [BNQ*1024];

// ---------------- LayerNorm: one block (256 thr) per row, C=256 ----------
__global__ void __launch_bounds__(256) ln_kernel(const float* __restrict__ x,
    const float* __restrict__ w, const float* __restrict__ b,
    float* __restrict__ y)
{
    int row = blockIdx.x;
    float v = x[(size_t)row*C_ + threadIdx.x];
    float s = v, s2 = v*v;
    __shared__ float red[16];
    int lane = threadIdx.x & 31, wid = threadIdx.x >> 5;
    #pragma unroll
    for (int o = 16; o; o >>= 1) {
        s  += __shfl_xor_sync(0xffffffffu, s,  o);
        s2 += __shfl_xor_sync(0xffffffffu, s2, o);
    }
    if (lane == 0) { red[wid] = s; red[wid+8] = s2; }
    __syncthreads();
    float ts = 0.f, ts2 = 0.f;
    #pragma unroll
    for (int i = 0; i < 8; i++) { ts += red[i]; ts2 += red[i+8]; }
    float mean = ts * (1.f/C_);
    float var  = ts2 * (1.f/C_) - mean*mean;
    float r = rsqrtf(var + 1e-5f);
    y[(size_t)row*C_ + threadIdx.x] = (v - mean)*r*w[threadIdx.x] + b[threadIdx.x];
}

// ---------------- TF32 tensor-core GEMM (cp.async 4-stage) ---------------
#define NSTG 4
#define STG_WORDS 5120          // (128*20) A + (128*20) B per stage
#define SMEM_BYTES (NSTG*STG_WORDS*4)

__device__ __forceinline__ void cp16(unsigned dst, const void* src, bool pred) {
    int sz = pred ? 16 : 0;
    asm volatile("cp.async.cg.shared.global [%0], [%1], 16, %2;\n"
                 :: "r"(dst), "l"(src), "r"(sz));
}
__device__ __forceinline__ void cp_commit() {
    asm volatile("cp.async.commit_group;\n");
}
__device__ __forceinline__ void cp_wait2() {
    asm volatile("cp.async.wait_group 2;\n");
}

__device__ __forceinline__ void mma_tf32(float* d, const unsigned* a, const unsigned* b) {
    asm volatile(
      "mma.sync.aligned.m16n8k8.row.col.f32.tf32.tf32.f32 "
      "{%0,%1,%2,%3}, {%4,%5,%6,%7}, {%8,%9}, {%0,%1,%2,%3};\n"
      : "+f"(d[0]), "+f"(d[1]), "+f"(d[2]), "+f"(d[3])
      : "r"(a[0]), "r"(a[1]), "r"(a[2]), "r"(a[3]), "r"(b[0]), "r"(b[1]));
}

__device__ __forceinline__ void mma_bf16(float* d, const unsigned* a, const unsigned* b) {
    asm volatile(
      "mma.sync.aligned.m16n8k16.row.col.f32.bf16.bf16.f32 "
      "{%0,%1,%2,%3}, {%4,%5,%6,%7}, {%8,%9}, {%0,%1,%2,%3};\n"
      : "+f"(d[0]), "+f"(d[1]), "+f"(d[2]), "+f"(d[3])
      : "r"(a[0]), "r"(a[1]), "r"(a[2]), "r"(a[3]), "r"(b[0]), "r"(b[1]));
}

__device__ __forceinline__ unsigned pack2(float a, float b) {
    __nv_bfloat162 h = __floats2bfloat162_rn(a, b);
    return *(unsigned*)&h;
}

template<int ACT>   // 0 = none, 1 = exact GELU
__global__ void __launch_bounds__(256, 2) gemm_tc(const float* __restrict__ A,
    const float* __restrict__ W, const float* __restrict__ bias,
    const float* __restrict__ res, float* __restrict__ Co,
    int M, int N, int K)
{
    extern __shared__ unsigned sh[];    // NSTG stages: [A 128x20 | B 128x20]

    const int t    = threadIdx.x;
    const int warp = t >> 5;
    const int lane = t & 31;
    const int grp  = lane >> 2;      // 0..7
    const int t4   = lane & 3;       // 0..3
    const int wm   = warp & 1;       // 2 warp-rows of 64
    const int wn   = warp >> 1;      // 4 warp-cols of 32
    const int m0   = blockIdx.y * 128, n0 = blockIdx.x * 128;

    const int lrow = t >> 2;         // 0..63 (load row)
    const int lc4  = (t & 3) * 4;    // 0,4,8,12 (k offset)

    const float* Ag0 = A + (size_t)(m0 + lrow     ) * K + lc4;
    const float* Ag1 = Ag0 + (size_t)64 * K;
    const bool wok0 = (n0 + lrow     ) < N;
    const bool wok1 = (n0 + lrow + 64) < N;
    const float* Wg0 = W + (size_t)(wok0 ? (n0 + lrow     ) : 0) * K + lc4;
    const float* Wg1 = W + (size_t)(wok1 ? (n0 + lrow + 64) : 0) * K + lc4;

    const unsigned sbase = (unsigned)__cvta_generic_to_shared(sh);
    const unsigned dA0 = sbase + ((lrow      )*20 + lc4)*4;
    const unsigned dA1 = sbase + ((lrow + 64 )*20 + lc4)*4;
    const unsigned dB0 = sbase + (2560 + (lrow     )*20 + lc4)*4;
    const unsigned dB1 = sbase + (2560 + (lrow + 64)*20 + lc4)*4;

    float acc[4][4][4];
    #pragma unroll
    for (int i = 0; i < 4; i++)
        #pragma unroll
        for (int j = 0; j < 4; j++)
            #pragma unroll
            for (int r = 0; r < 4; r++) acc[i][j][r] = 0.f;

    const int iters = K >> 4;

    // prologue: stages 0..2
    #pragma unroll
    for (int s = 0; s < NSTG - 1; s++) {
        unsigned off = s * STG_WORDS * 4;
        int ko = s << 4;
        cp16(dA0 + off, Ag0 + ko, true);
        cp16(dA1 + off, Ag1 + ko, true);
        cp16(dB0 + off, Wg0 + ko, wok0);
        cp16(dB1 + off, Wg1 + ko, wok1);
        cp_commit();
    }

    int s = 0;
    for (int it = 0; it < iters; it++) {
        cp_wait2();
        __syncthreads();

        const unsigned* Asm = sh + s * STG_WORDS;
        const unsigned* Bsm = Asm + 2560;

        #pragma unroll
        for (int kb = 0; kb < 16; kb += 8) {
            unsigned af[4][4], bf[4][2];
            #pragma unroll
            for (int mt = 0; mt < 4; mt++) {
                int m = wm*64 + mt*16 + grp;
                af[mt][0] = Asm[(m  )*20 + kb + t4];
                af[mt][1] = Asm[(m+8)*20 + kb + t4];
                af[mt][2] = Asm[(m  )*20 + kb + t4 + 4];
                af[mt][3] = Asm[(m+8)*20 + kb + t4 + 4];
            }
            #pragma unroll
            for (int nt = 0; nt < 4; nt++) {
                int n = wn*32 + nt*8 + grp;
                bf[nt][0] = Bsm[n*20 + kb + t4];
                bf[nt][1] = Bsm[n*20 + kb + t4 + 4];
            }
            #pragma unroll
            for (int mt = 0; mt < 4; mt++)
                #pragma unroll
                for (int nt = 0; nt < 4; nt++)
                    mma_tf32(acc[mt][nt], af[mt], bf[nt]);
        }

        int kt = it + NSTG - 1;
        if (kt < iters) {
            int sn = s + NSTG - 1; if (sn >= NSTG) sn -= NSTG;
            unsigned off = sn * STG_WORDS * 4;
            int ko = kt << 4;
            cp16(dA0 + off, Ag0 + ko, true);
            cp16(dA1 + off, Ag1 + ko, true);
            cp16(dB0 + off, Wg0 + ko, wok0);
            cp16(dB1 + off, Wg1 + ko, wok1);
        }
        cp_commit();
        if (++s == NSTG) s = 0;
    }

    // epilogue
    #pragma unroll
    for (int mt = 0; mt < 4; mt++) {
        #pragma unroll
        for (int nt = 0; nt < 4; nt++) {
            int rbase = m0 + wm*64 + mt*16 + grp;
            int cbase = n0 + wn*32 + nt*8 + t4*2;
            #pragma unroll
            for (int rr = 0; rr < 2; rr++) {
                int m = rbase + rr*8;
                #pragma unroll
                for (int cc = 0; cc < 2; cc++) {
                    int n = cbase + cc;
                    if (n < N) {
                        float v = acc[mt][nt][rr*2 + cc] + bias[n];
                        if (ACT == 1) v = 0.5f*v*(1.f + erff(v*0.70710678118654752f));
                        if (res) v += res[(size_t)m*N + n];
                        Co[(size_t)m*N + n] = v;
                    }
                }
            }
        }
    }
}

// ---------------- Flash self-attention (bf16 MMA, m16n8k16) ---------------
// CTA = (b, h, 128-query tile). 8 warps x 16 query rows.
// P accumulator layout == bf16 A-fragment layout after packing: zero shfls.
// Ksp stride 20 / Vtp stride 36: conflict-free fragment reads.
__global__ void __launch_bounds__(256) attn_mma(const float* __restrict__ qkv,
                                                float* __restrict__ out)
{
    __shared__ unsigned Ksp[64][20];   // K tile, bf16 pairs packed along d
    __shared__ unsigned Vtp[32][36];   // V^T tile, bf16 pairs packed along seq

    const int bx = blockIdx.x;
    const int qt = bx & 7;
    const int h  = (bx >> 3) & 7;
    const int b  = bx >> 6;
    const int t = threadIdx.x, warp = t >> 5, lane = t & 31;
    const int grp = lane >> 2, t4 = lane & 3;
    const int q0 = qt*128, wq = warp*16;

    const float scale = 0.17677669529663687f;  // 1/sqrt(32)

    // Q fragments bf16 (m16 x k32 = 2 k-blocks of 16)
    const float* qb = qkv + ((size_t)(b*NQ_ + q0 + wq))*768 + h*32;
    unsigned Qf[2][4];
    #pragma unroll
    for (int kb = 0; kb < 2; kb++) {
        int c0 = kb*16 + 2*t4;
        Qf[kb][0] = pack2(qb[(size_t)(grp  )*768 + c0    ]*scale, qb[(size_t)(grp  )*768 + c0 + 1]*scale);
        Qf[kb][1] = pack2(qb[(size_t)(grp+8)*768 + c0    ]*scale, qb[(size_t)(grp+8)*768 + c0 + 1]*scale);
        Qf[kb][2] = pack2(qb[(size_t)(grp  )*768 + c0 + 8]*scale, qb[(size_t)(grp  )*768 + c0 + 9]*scale);
        Qf[kb][3] = pack2(qb[(size_t)(grp+8)*768 + c0 + 8]*scale, qb[(size_t)(grp+8)*768 + c0 + 9]*scale);
    }

    float m_a = -1e30f, m_b = -1e30f, l_a = 0.f, l_b = 0.f;
    float oac[4][4];
    #pragma unroll
    for (int i = 0; i < 4; i++)
        #pragma unroll
        for (int j = 0; j < 4; j++) oac[i][j] = 0.f;

    const float* kg = qkv + (size_t)(b*NQ_)*768 + 256 + h*32;
    const float* vg = qkv + (size_t)(b*NQ_)*768 + 512 + h*32;

    const int lrow = t >> 2, lj = t & 3;      // K loader
    const int sp = t >> 3, dg = (t & 7) * 4;  // V loader

    for (int kt = 0; kt < 16; kt++) {
        __syncthreads();
        {   // K tile [64][32] -> packed pairs along d
            const float* src = kg + (size_t)(kt*64 + lrow)*768 + lj*8;
            float4 v0 = *(const float4*)(src);
            float4 v1 = *(const float4*)(src + 4);
            uint4 w;
            w.x = pack2(v0.x, v0.y); w.y = pack2(v0.z, v0.w);
            w.z = pack2(v1.x, v1.y); w.w = pack2(v1.z, v1.w);
            *(uint4*)&Ksp[lrow][lj*4] = w;
            // V tile transposed: pairs along seq
            const float* sv = vg + (size_t)(kt*64 + 2*sp)*768 + dg;
            float4 a = *(const float4*)(sv);
            float4 c = *(const float4*)(sv + 768);
            Vtp[dg+0][sp] = pack2(a.x, c.x);
            Vtp[dg+1][sp] = pack2(a.y, c.y);
            Vtp[dg+2][sp] = pack2(a.z, c.z);
            Vtp[dg+3][sp] = pack2(a.w, c.w);
        }
        __syncthreads();

        // S = Q @ K^T : m16 x n64
        float sacc[8][4];
        #pragma unroll
        for (int nt = 0; nt < 8; nt++)
            #pragma unroll
            for (int r = 0; r < 4; r++) sacc[nt][r] = 0.f;
        #pragma unroll
        for (int kb = 0; kb < 2; kb++) {
            #pragma unroll
            for (int nt = 0; nt < 8; nt++) {
                unsigned bf[2];
                bf[0] = Ksp[nt*8 + grp][kb*8 + t4];
                bf[1] = Ksp[nt*8 + grp][kb*8 + 4 + t4];
                mma_bf16(sacc[nt], Qf[kb], bf);
            }
        }

        // online softmax (rows grp and grp+8)
        float mx_a = -1e30f, mx_b = -1e30f;
        #pragma unroll
        for (int nt = 0; nt < 8; nt++) {
            mx_a = fmaxf(mx_a, fmaxf(sacc[nt][0], sacc[nt][1]));
            mx_b = fmaxf(mx_b, fmaxf(sacc[nt][2], sacc[nt][3]));
        }
        mx_a = fmaxf(mx_a, __shfl_xor_sync(0xffffffffu, mx_a, 1));
        mx_a = fmaxf(mx_a, __shfl_xor_sync(0xffffffffu, mx_a, 2));
        mx_b = fmaxf(mx_b, __shfl_xor_sync(0xffffffffu, mx_b, 1));
        mx_b = fmaxf(mx_b, __shfl_xor_sync(0xffffffffu, mx_b, 2));
        float mna = fmaxf(m_a, mx_a), mnb = fmaxf(m_b, mx_b);
        float ca = __expf(m_a - mna), cb = __expf(m_b - mnb);
        float sa = 0.f, sb = 0.f;
        #pragma unroll
        for (int nt = 0; nt < 8; nt++) {
            sacc[nt][0] = __expf(sacc[nt][0] - mna);
            sacc[nt][1] = __expf(sacc[nt][1] - mna);
            sacc[nt][2] = __expf(sacc[nt][2] - mnb);
            sacc[nt][3] = __expf(sacc[nt][3] - mnb);
            sa += sacc[nt][0] + sacc[nt][1];
            sb += sacc[nt][2] + sacc[nt][3];
        }
        sa += __shfl_xor_sync(0xffffffffu, sa, 1);
        sa += __shfl_xor_sync(0xffffffffu, sa, 2);
        sb += __shfl_xor_sync(0xffffffffu, sb, 1);
        sb += __shfl_xor_sync(0xffffffffu, sb, 2);
        l_a = l_a*ca + sa;  l_b = l_b*cb + sb;
        m_a = mna;          m_b = mnb;
        #pragma unroll
        for (int nt = 0; nt < 4; nt++) {
            oac[nt][0] *= ca; oac[nt][1] *= ca;
            oac[nt][2] *= cb; oac[nt][3] *= cb;
        }

        // O += P @ V : P accumulator layout == A-fragment layout (packed)
        #pragma unroll
        for (int kb = 0; kb < 4; kb++) {
            unsigned pa[4];
            pa[0] = pack2(sacc[2*kb  ][0], sacc[2*kb  ][1]);
            pa[1] = pack2(sacc[2*kb  ][2], sacc[2*kb  ][3]);
            pa[2] = pack2(sacc[2*kb+1][0], sacc[2*kb+1][1]);
            pa[3] = pack2(sacc[2*kb+1][2], sacc[2*kb+1][3]);
            #pragma unroll
            for (int nt = 0; nt < 4; nt++) {
                unsigned bf[2];
                bf[0] = Vtp[nt*8 + grp][kb*8 + t4];
                bf[1] = Vtp[nt*8 + grp][kb*8 + 4 + t4];
                mma_bf16(oac[nt], pa, bf);
            }
        }
    }

    float inva = 1.f / l_a, invb = 1.f / l_b;
    float* ob = out + ((size_t)(b*NQ_ + q0 + wq))*C_ + h*32;
    #pragma unroll
    for (int nt = 0; nt < 4; nt++) {
        ob[(size_t)(grp  )*C_ + nt*8 + 2*t4    ] = oac[nt][0]*inva;
        ob[(size_t)(grp  )*C_ + nt*8 + 2*t4 + 1] = oac[nt][1]*inva;
        ob[(size_t)(grp+8)*C_ + nt*8 + 2*t4    ] = oac[nt][2]*invb;
        ob[(size_t)(grp+8)*C_ + nt*8 + 2*t4 + 1] = oac[nt][3]*invb;
    }
}

// ---------------- reference points: sigmoid(q @ ref_w^T + ref_b) ---------
__global__ void __launch_bounds__(256) ref_kernel(const float* __restrict__ q,
    const float* __restrict__ rw, const float* __restrict__ rb,
    float* __restrict__ outp)
{
    int wid = threadIdx.x >> 5, lane = threadIdx.x & 31;
    int row = blockIdx.x*8 + wid;
    const float* x = q + (size_t)row*C_;
    float s0 = 0.f, s1 = 0.f;
    #pragma unroll
    for (int i = 0; i < 8; i++) {
        float xv = x[lane + 32*i];
        s0 += xv * rw[lane + 32*i];
        s1 += xv * rw[C_ + lane + 32*i];
    }
    #pragma unroll
    for (int o = 16; o; o >>= 1) {
        s0 += __shfl_xor_sync(0xffffffffu, s0, o);
        s1 += __shfl_xor_sync(0xffffffffu, s1, o);
    }
    if (lane == 0) {
        outp[(size_t)row*2    ] = 1.f/(1.f + __expf(-(s0 + rb[0])));
        outp[(size_t)row*2 + 1] = 1.f/(1.f + __expf(-(s1 + rb[1])));
    }
}

// ---------------- MSDeformAttn sampling: warp per (b,q,h), lane = channel -
__global__ void __launch_bounds__(256) msdeform_kernel(const float* __restrict__ value,
    const float* __restrict__ ref, const float* __restrict__ so,
    const float* __restrict__ aw, float* __restrict__ outp)
{
    const int wid = threadIdx.x >> 5, lane = threadIdx.x & 31;
    const int gw = blockIdx.x*8 + wid;      // ((b*NQ+q)*8 + h)
    const int h  = gw & 7;
    const int bq = gw >> 3;
    const int b  = bq >> 10;

    // softmax over 24 attention-weight logits (lanes 0..23)
    float logit = -1e30f;
    if (lane < 24) logit = aw[(size_t)bq*192 + h*24 + lane];
    float mx = logit;
    #pragma unroll
    for (int o = 16; o; o >>= 1) mx = fmaxf(mx, __shfl_xor_sync(0xffffffffu, mx, o));
    float e = (lane < 24) ? __expf(logit - mx) : 0.f;
    float ssum = e;
    #pragma unroll
    for (int o = 16; o; o >>= 1) ssum += __shfl_xor_sync(0xffffffffu, ssum, o);
    float pw = e / ssum;

    // sampling offsets (lanes 0..23 hold their own point)
    float offx = 0.f, offy = 0.f;
    if (lane < 24) {
        int l = lane >> 3, p = lane & 7;
        const float* sp = so + (size_t)bq*384 + ((size_t)((h*3 + l)*8 + p))*2;
        offx = sp[0]; offy = sp[1];
    }
    float rx = ref[(size_t)bq*2], ry = ref[(size_t)bq*2 + 1];

    const int HL[3] = {128, 64, 32};
    const int WL[3] = {128, 64, 32};
    const int ST[3] = {0, 16384, 20480};

    float acc = 0.f;
    #pragma unroll
    for (int l = 0; l < 3; l++) {
        const int h_l = HL[l], w_l = WL[l], start = ST[l];
        const float gxb = rx * (float)w_l - 0.5f;
        const float gyb = ry * (float)h_l - 0.5f;
        const float* vb = value + ((size_t)(b*S_ + start))*C_ + h*32 + lane;
        #pragma unroll
        for (int p = 0; p < 8; p++) {
            int lp = l*8 + p;
            float ox = __shfl_sync(0xffffffffu, offx, lp);
            float oy = __shfl_sync(0xffffffffu, offy, lp);
            float w  = __shfl_sync(0xffffffffu, pw,   lp);
            float gx = gxb + ox;
            float gy = gyb + oy;
            float x0f = floorf(gx), y0f = floorf(gy);
            float lx = gx - x0f, ly = gy - y0f;
            int x0 = (int)x0f, y0 = (int)y0f;
            float w00 = (1.f-lx)*(1.f-ly)*w;
            float w01 = lx*(1.f-ly)*w;
            float w10 = (1.f-lx)*ly*w;
            float w11 = lx*ly*w;
            bool vx0 = (x0   >= 0) & (x0   < w_l);
            bool vx1 = (x0+1 >= 0) & (x0+1 < w_l);
            if (y0 >= 0 && y0 < h_l) {
                const float* rowp = vb + (size_t)y0*w_l*C_;
                if (vx0) acc += w00 * rowp[(size_t)x0*C_];
                if (vx1) acc += w01 * rowp[(size_t)(x0+1)*C_];
            }
            if (y0+1 >= 0 && y0+1 < h_l) {
                const float* rowp = vb + (size_t)(y0+1)*w_l*C_;
                if (vx0) acc += w10 * rowp[(size_t)x0*C_];
                if (vx1) acc += w11 * rowp[(size_t)(x0+1)*C_];
            }
        }
    }
    outp[(size_t)bq*C_ + h*32 + lane] = acc;
}

// ---------------- launch ----------------
extern "C" void kernel_launch(void* const* d_in, const int* in_sizes, int n_in,
                              void* d_out, int out_size)
{
    const float* tgt    = (const float*)d_in[0];
    const float* memory = (const float*)d_in[1];
    const float* n1w = (const float*)d_in[2];
    const float* n1b = (const float*)d_in[3];
    const float* inw = (const float*)d_in[4];
    const float* inb = (const float*)d_in[5];
    const float* outw= (const float*)d_in[6];
    const float* outb= (const float*)d_in[7];
    const float* n2w = (const float*)d_in[8];
    const float* n2b = (const float*)d_in[9];
    const float* refw= (const float*)d_in[10];
    const float* refb= (const float*)d_in[11];
    const float* sow = (const float*)d_in[12];
    const float* sob = (const float*)d_in[13];
    const float* aww = (const float*)d_in[14];
    const float* awb = (const float*)d_in[15];
    const float* vpw = (const float*)d_in[16];
    const float* vpb = (const float*)d_in[17];
    const float* opw = (const float*)d_in[18];
    const float* opb = (const float*)d_in[19];
    const float* n3w = (const float*)d_in[20];
    const float* n3b = (const float*)d_in[21];
    const float* l1w = (const float*)d_in[22];
    const float* l1b = (const float*)d_in[23];
    const float* l2w = (const float*)d_in[24];
    const float* l2b = (const float*)d_in[25];

    float *q, *qkv, *attn, *tgt2, *tgt3, *val, *so, *aw, *refo, *ca, *ff1;
    cudaGetSymbolAddress((void**)&q,    g_q);
    cudaGetSymbolAddress((void**)&qkv,  g_qkv);
    cudaGetSymbolAddress((void**)&attn, g_attn);
    cudaGetSymbolAddress((void**)&tgt2, g_tgt2);
    cudaGetSymbolAddress((void**)&tgt3, g_tgt3);
    cudaGetSymbolAddress((void**)&val,  g_val);
    cudaGetSymbolAddress((void**)&so,   g_so);
    cudaGetSymbolAddress((void**)&aw,   g_aw);
    cudaGetSymbolAddress((void**)&refo, g_ref);
    cudaGetSymbolAddress((void**)&ca,   g_ca);
    cudaGetSymbolAddress((void**)&ff1,  g_ff1);

    // one-time resources (host-side only; no device memory involved)
    static cudaStream_t s2 = 0;
    static cudaEvent_t evFork = 0, evJoin = 0;
    if (!s2) {
        cudaStreamCreateWithFlags(&s2, cudaStreamNonBlocking);
        cudaEventCreateWithFlags(&evFork, cudaEventDisableTiming);
        cudaEventCreateWithFlags(&evJoin, cudaEventDisableTiming);
        cudaFuncSetAttribute(gemm_tc<0>, cudaFuncAttributeMaxDynamicSharedMemorySize, SMEM_BYTES);
        cudaFuncSetAttribute(gemm_tc<1>, cudaFuncAttributeMaxDynamicSharedMemorySize, SMEM_BYTES);
    }

    // ---- fork: value projection runs concurrently on s2 ----
    cudaEventRecord(evFork, 0);
    cudaStreamWaitEvent(s2, evFork, 0);
    gemm_tc<0><<<dim3(C_/128, BS_/128), 256, SMEM_BYTES, s2>>>(memory, vpw, vpb, nullptr, val, BS_, C_, C_);
    cudaEventRecord(evJoin, s2);

    // ---- main chain (stream 0) ----
    // 1. q1 = LN(tgt)
    ln_kernel<<<BNQ, 256>>>(tgt, n1w, n1b, q);
    // 2. qkv = q1 @ in_w^T + in_b
    gemm_tc<0><<<dim3(768/128, BNQ/128), 256, SMEM_BYTES>>>(q, inw, inb, nullptr, qkv, BNQ, 768, C_);
    // 3. self-attention (bf16 tensor cores)
    attn_mma<<<B_*8*8, 256>>>(qkv, attn);
    // 4. tgt2 = tgt + attn @ out_w^T + out_b
    gemm_tc<0><<<dim3(C_/128, BNQ/128), 256, SMEM_BYTES>>>(attn, outw, outb, tgt, tgt2, BNQ, C_, C_);
    // 5. q2 = LN(tgt2)
    ln_kernel<<<BNQ, 256>>>(tgt2, n2w, n2b, q);
    // 6. sampling offsets
    gemm_tc<0><<<dim3(3, BNQ/128), 256, SMEM_BYTES>>>(q, sow, sob, nullptr, so, BNQ, 384, C_);
    // 7. attention weight logits (N=192, guarded)
    gemm_tc<0><<<dim3(2, BNQ/128), 256, SMEM_BYTES>>>(q, aww, awb, nullptr, aw, BNQ, 192, C_);
    // 8. reference points
    ref_kernel<<<BNQ/8, 256>>>(q, refw, refb, refo);

    // ---- join: need value ready before sampling ----
    cudaStreamWaitEvent(0, evJoin, 0);

    // 9. deformable sampling
    msdeform_kernel<<<BNQ, 256>>>(val, refo, so, aw, ca);
    // 10. tgt3 = tgt2 + ca @ op_w^T + op_b
    gemm_tc<0><<<dim3(C_/128, BNQ/128), 256, SMEM_BYTES>>>(ca, opw, opb, tgt2, tgt3, BNQ, C_, C_);
    // 11. q3 = LN(tgt3)
    ln_kernel<<<BNQ, 256>>>(tgt3, n3w, n3b, q);
    // 12. ff1 = gelu(q3 @ l1_w^T + l1_b)
    gemm_tc<1><<<dim3(1024/128, BNQ/128), 256, SMEM_BYTES>>>(q, l1w, l1b, nullptr, ff1, BNQ, 1024, C_);
    // 13. out = tgt3 + ff1 @ l2_w^T + l2_b
    gemm_tc<0><<<dim3(C_/128, BNQ/128), 256, SMEM_BYTES>>>(ff1, l2w, l2b, tgt3, (float*)d_out, BNQ, C_, 1024);
}